// round 1
// baseline (speedup 1.0000x reference)
#include <cuda_runtime.h>
#include <mma.h>

using namespace nvcuda;

#define B_  4
#define T_  2048
#define D_  1024
#define H_  16
#define DKH 64

// ---------------- scratch (static device globals; no runtime alloc) --------
__device__ float g_qh[(size_t)B_ * T_ * D_];
__device__ float g_kh[(size_t)B_ * T_ * D_];
__device__ float g_vh[(size_t)B_ * T_ * D_];
__device__ float g_ao[(size_t)B_ * T_ * D_];
__device__ float g_x [(size_t)B_ * T_ * D_];

// ---------------- tf32 WMMA GEMM: C = A@W + bias (+res) --------------------
// BM=128, BN=64, BK=32, 256 threads (8 warps: 4 row x 2 col, 32x32 per warp)
template<bool HAS_RES>
__global__ void gemm_tf32_kernel(const float* __restrict__ A,
                                 const float* __restrict__ W,
                                 const float* __restrict__ bias,
                                 const float* __restrict__ res,
                                 float* __restrict__ C,
                                 int M, int N, int K) {
    constexpr int BM = 128, BN = 64, BK = 32;
    constexpr int LDA = 40, LDB = 72, LDC = 72;

    __shared__ float sm[BM * LDC];      // 9216 floats = 36.9KB
    float* As = sm;                     // BM*LDA = 5120
    float* Bs = sm + BM * LDA;          // BK*LDB = 2304  (fits)
    float* Cs = sm;                     // reused for epilogue

    const int tid  = threadIdx.x;
    const int warp = tid >> 5;
    const int wr   = warp & 3;          // 0..3 -> row block of 32
    const int wc   = warp >> 2;         // 0..1 -> col block of 32
    const int m0   = blockIdx.y * BM;
    const int n0   = blockIdx.x * BN;

    wmma::fragment<wmma::accumulator, 16, 16, 8, float> acc[2][2];
    #pragma unroll
    for (int i = 0; i < 2; i++)
        #pragma unroll
        for (int j = 0; j < 2; j++)
            wmma::fill_fragment(acc[i][j], 0.0f);

    for (int k0 = 0; k0 < K; k0 += BK) {
        __syncthreads();
        // load A tile 128x32
        #pragma unroll
        for (int it = 0; it < (BM * BK) / 256; it++) {
            int idx = tid + it * 256;
            int r = idx >> 5, c = idx & 31;
            As[r * LDA + c] = wmma::__float_to_tf32(A[(size_t)(m0 + r) * K + k0 + c]);
        }
        // load W tile 32x64
        #pragma unroll
        for (int it = 0; it < (BK * BN) / 256; it++) {
            int idx = tid + it * 256;
            int r = idx >> 6, c = idx & 63;
            Bs[r * LDB + c] = wmma::__float_to_tf32(W[(size_t)(k0 + r) * N + n0 + c]);
        }
        __syncthreads();

        #pragma unroll
        for (int kk = 0; kk < BK / 8; kk++) {
            wmma::fragment<wmma::matrix_a, 16, 16, 8, wmma::precision::tf32, wmma::row_major> af[2];
            wmma::fragment<wmma::matrix_b, 16, 16, 8, wmma::precision::tf32, wmma::row_major> bf[2];
            #pragma unroll
            for (int i = 0; i < 2; i++)
                wmma::load_matrix_sync(af[i], As + (wr * 32 + i * 16) * LDA + kk * 8, LDA);
            #pragma unroll
            for (int j = 0; j < 2; j++)
                wmma::load_matrix_sync(bf[j], Bs + (kk * 8) * LDB + wc * 32 + j * 16, LDB);
            #pragma unroll
            for (int i = 0; i < 2; i++)
                #pragma unroll
                for (int j = 0; j < 2; j++)
                    wmma::mma_sync(acc[i][j], af[i], bf[j], acc[i][j]);
        }
    }

    __syncthreads();
    #pragma unroll
    for (int i = 0; i < 2; i++)
        #pragma unroll
        for (int j = 0; j < 2; j++)
            wmma::store_matrix_sync(Cs + (wr * 32 + i * 16) * LDC + wc * 32 + j * 16,
                                    acc[i][j], LDC, wmma::mem_row_major);
    __syncthreads();

    #pragma unroll
    for (int it = 0; it < (BM * BN) / 256; it++) {
        int idx = tid + it * 256;
        int r = idx >> 6, c = idx & 63;
        float v = Cs[r * LDC + c] + bias[n0 + c];
        if (HAS_RES) v += res[(size_t)(m0 + r) * N + n0 + c];
        C[(size_t)(m0 + r) * N + n0 + c] = v;
    }
}

// ---------------- flash attention (tf32 WMMA), 64x64 tiles -----------------
// grid (T/64, H, B), 128 threads (4 warps; warp w owns output rows w*16..w*16+15)
__global__ void attn_kernel(const float* __restrict__ Qh,
                            const float* __restrict__ Kh,
                            const float* __restrict__ Vh,
                            const int*   __restrict__ mask,
                            float* __restrict__ Out) {
    constexpr int LD = 72;
    extern __shared__ float smdyn[];
    float* Qs     = smdyn;                 // 64*72
    float* Ks     = Qs + 64 * LD;          // 64*72
    float* Vs     = Ks + 64 * LD;          // 64*72
    float* Ss     = Vs + 64 * LD;          // 64*72
    float* alphaM = Ss + 64 * LD;          // 64*16
    float* mrow   = alphaM + 64 * 16;      // 64
    float* lrow   = mrow + 64;             // 64
    int*   Ms     = (int*)(lrow + 64);     // 64*64 ints

    const int tid  = threadIdx.x;
    const int warp = tid >> 5;
    const int q0   = blockIdx.x * 64;
    const int h    = blockIdx.y;
    const int b    = blockIdx.z;

    const float* Qg = Qh + ((size_t)b * T_ + q0) * D_ + h * DKH;

    for (int i = tid; i < 64 * 64; i += 128) {
        int r = i >> 6, c = i & 63;
        Qs[r * LD + c] = wmma::__float_to_tf32(Qg[(size_t)r * D_ + c]);
    }
    if (tid < 64) { mrow[tid] = -1e30f; lrow[tid] = 0.0f; }

    wmma::fragment<wmma::accumulator, 16, 16, 8, float> o_frag[4];
    #pragma unroll
    for (int j = 0; j < 4; j++) wmma::fill_fragment(o_frag[j], 0.0f);
    __syncthreads();

    for (int kt = 0; kt < T_ / 64; kt++) {
        const int k0 = kt * 64;
        const float* Kg = Kh + ((size_t)b * T_ + k0) * D_ + h * DKH;
        const float* Vg = Vh + ((size_t)b * T_ + k0) * D_ + h * DKH;
        const int*   Mg = mask + ((size_t)b * T_ + q0) * T_ + k0;

        for (int i = tid; i < 64 * 64; i += 128) {
            int r = i >> 6, c = i & 63;
            Ks[r * LD + c] = wmma::__float_to_tf32(Kg[(size_t)r * D_ + c]);
            Vs[r * LD + c] = wmma::__float_to_tf32(Vg[(size_t)r * D_ + c]);
            Ms[i] = Mg[(size_t)r * T_ + c];
        }
        __syncthreads();

        // S = Q @ K^T  (warp computes rows [warp*16, +16), all 64 cols)
        {
            wmma::fragment<wmma::matrix_a, 16, 16, 8, wmma::precision::tf32, wmma::row_major> af;
            wmma::fragment<wmma::matrix_b, 16, 16, 8, wmma::precision::tf32, wmma::col_major> bf;
            wmma::fragment<wmma::accumulator, 16, 16, 8, float> sfr[4];
            #pragma unroll
            for (int j = 0; j < 4; j++) wmma::fill_fragment(sfr[j], 0.0f);
            #pragma unroll
            for (int kk = 0; kk < 8; kk++) {
                wmma::load_matrix_sync(af, Qs + (warp * 16) * LD + kk * 8, LD);
                #pragma unroll
                for (int j = 0; j < 4; j++) {
                    wmma::load_matrix_sync(bf, Ks + (j * 16) * LD + kk * 8, LD);
                    wmma::mma_sync(sfr[j], af, bf, sfr[j]);
                }
            }
            #pragma unroll
            for (int j = 0; j < 4; j++)
                wmma::store_matrix_sync(Ss + (warp * 16) * LD + j * 16, sfr[j], LD,
                                        wmma::mem_row_major);
        }
        __syncthreads();

        // masked online softmax: 2 threads per row (halves of 32 cols)
        {
            const int r = tid >> 1, half = tid & 1;
            const int cbase = half * 32;
            float sloc[32];
            float mx = -1e30f;
            #pragma unroll
            for (int c = 0; c < 32; c++) {
                float s = Ss[r * LD + cbase + c];
                int mk = Ms[(r << 6) + cbase + c];
                s = mk ? s : -1e30f;
                sloc[c] = s;
                mx = fmaxf(mx, s);
            }
            mx = fmaxf(mx, __shfl_xor_sync(0xffffffffu, mx, 1));
            float mold = mrow[r];
            float mnew = fmaxf(mold, mx);
            float lsum = 0.0f;
            #pragma unroll
            for (int c = 0; c < 32; c++) {
                float p = (sloc[c] > -1e29f) ? __expf(sloc[c] - mnew) : 0.0f;
                lsum += p;
                Ss[r * LD + cbase + c] = wmma::__float_to_tf32(p);
            }
            lsum += __shfl_xor_sync(0xffffffffu, lsum, 1);
            float alpha = __expf(mold - mnew);
            if (half == 0) { mrow[r] = mnew; lrow[r] = lrow[r] * alpha + lsum; }
            #pragma unroll
            for (int j = 0; j < 8; j++)
                alphaM[(r << 4) + half * 8 + j] = alpha;
        }
        __syncthreads();

        // O = O*alpha + P @ V (alpha applied via accumulator-layout fragment)
        {
            wmma::fragment<wmma::accumulator, 16, 16, 8, float> afr;
            wmma::load_matrix_sync(afr, alphaM + warp * 16 * 16, 16, wmma::mem_row_major);
            #pragma unroll
            for (int j = 0; j < 4; j++)
                #pragma unroll
                for (int e = 0; e < afr.num_elements; e++)
                    o_frag[j].x[e] *= afr.x[e];

            wmma::fragment<wmma::matrix_a, 16, 16, 8, wmma::precision::tf32, wmma::row_major> pf;
            wmma::fragment<wmma::matrix_b, 16, 16, 8, wmma::precision::tf32, wmma::row_major> vf;
            #pragma unroll
            for (int kk = 0; kk < 8; kk++) {
                wmma::load_matrix_sync(pf, Ss + (warp * 16) * LD + kk * 8, LD);
                #pragma unroll
                for (int j = 0; j < 4; j++) {
                    wmma::load_matrix_sync(vf, Vs + (kk * 8) * LD + j * 16, LD);
                    wmma::mma_sync(o_frag[j], pf, vf, o_frag[j]);
                }
            }
        }
        __syncthreads();   // protect Ks/Vs/Ms/Ss before next-iteration overwrite
    }

    // epilogue: O / (l + 1e-15)
    #pragma unroll
    for (int j = 0; j < 4; j++)
        wmma::store_matrix_sync(Ss + (warp * 16) * LD + j * 16, o_frag[j], LD,
                                wmma::mem_row_major);
    __syncthreads();
    for (int i = tid; i < 64 * 64; i += 128) {
        int r = i >> 6, c = i & 63;
        float v = Ss[r * LD + c] / (lrow[r] + 1e-15f);
        Out[((size_t)b * T_ + q0 + r) * D_ + h * DKH + c] = v;
    }
}

// ---------------- LayerNorm over D=1024, one block per row -----------------
__global__ void ln_kernel(const float* __restrict__ X,
                          const float* __restrict__ gamma,
                          const float* __restrict__ beta,
                          float* __restrict__ Out) {
    const int row = blockIdx.x;
    const int tid = threadIdx.x;              // 256 threads, 4 floats each
    const float* x = X + (size_t)row * D_;

    __shared__ float red[8];
    __shared__ float s_mu, s_inv;

    float4 v = ((const float4*)x)[tid];
    float s = v.x + v.y + v.z + v.w;
    #pragma unroll
    for (int o = 16; o > 0; o >>= 1) s += __shfl_xor_sync(0xffffffffu, s, o);
    if ((tid & 31) == 0) red[tid >> 5] = s;
    __syncthreads();
    if (tid == 0) {
        float t = 0.0f;
        #pragma unroll
        for (int i = 0; i < 8; i++) t += red[i];
        s_mu = t * (1.0f / D_);
    }
    __syncthreads();
    const float mu = s_mu;

    float dx = v.x - mu, dy = v.y - mu, dz = v.z - mu, dw = v.w - mu;
    float s2 = dx * dx + dy * dy + dz * dz + dw * dw;
    #pragma unroll
    for (int o = 16; o > 0; o >>= 1) s2 += __shfl_xor_sync(0xffffffffu, s2, o);
    if ((tid & 31) == 0) red[tid >> 5] = s2;
    __syncthreads();
    if (tid == 0) {
        float t = 0.0f;
        #pragma unroll
        for (int i = 0; i < 8; i++) t += red[i];
        s_inv = rsqrtf(t * (1.0f / D_) + 1e-5f);
    }
    __syncthreads();
    const float inv = s_inv;

    const int c = tid * 4;
    float4 g = ((const float4*)(gamma + c))[0];
    float4 bb = ((const float4*)(beta + c))[0];
    float4 o;
    o.x = dx * inv * g.x + bb.x;
    o.y = dy * inv * g.y + bb.y;
    o.z = dz * inv * g.z + bb.z;
    o.w = dw * inv * g.w + bb.w;
    ((float4*)(Out + (size_t)row * D_))[tid] = o;
}

// ---------------- launch ----------------------------------------------------
extern "C" void kernel_launch(void* const* d_in, const int* in_sizes, int n_in,
                              void* d_out, int out_size) {
    const float* q     = (const float*)d_in[0];
    const float* k     = (const float*)d_in[1];
    const float* v     = (const float*)d_in[2];
    const int*   mask  = (const int*)  d_in[3];
    const float* Wq    = (const float*)d_in[4];
    const float* bq    = (const float*)d_in[5];
    const float* Wk    = (const float*)d_in[6];
    const float* bk    = (const float*)d_in[7];
    const float* Wv    = (const float*)d_in[8];
    const float* bv    = (const float*)d_in[9];
    const float* Wo    = (const float*)d_in[10];
    const float* bo    = (const float*)d_in[11];
    const float* gamma = (const float*)d_in[12];
    const float* beta  = (const float*)d_in[13];
    float* out = (float*)d_out;

    float *qh, *kh, *vh, *ao, *xb;
    cudaGetSymbolAddress((void**)&qh, g_qh);
    cudaGetSymbolAddress((void**)&kh, g_kh);
    cudaGetSymbolAddress((void**)&vh, g_vh);
    cudaGetSymbolAddress((void**)&ao, g_ao);
    cudaGetSymbolAddress((void**)&xb, g_x);

    const int M = B_ * T_;   // 8192
    const int N = D_;        // 1024
    const int K = D_;        // 1024

    dim3 gg(N / 64, M / 128);      // (16, 64)
    gemm_tf32_kernel<false><<<gg, 256>>>(q, Wq, bq, nullptr, qh, M, N, K);
    gemm_tf32_kernel<false><<<gg, 256>>>(k, Wk, bk, nullptr, kh, M, N, K);
    gemm_tf32_kernel<false><<<gg, 256>>>(v, Wv, bv, nullptr, vh, M, N, K);

    size_t smem = (size_t)(4 * 64 * 72 + 64 * 16 + 128 + 64 * 64) * 4;  // 94720 B
    cudaFuncSetAttribute(attn_kernel, cudaFuncAttributeMaxDynamicSharedMemorySize,
                         (int)smem);
    dim3 ga(T_ / 64, H_, B_);      // (32, 16, 4)
    attn_kernel<<<ga, 128, smem>>>(qh, kh, vh, mask, ao);

    gemm_tf32_kernel<true><<<gg, 256>>>(ao, Wo, bo, q, xb, M, N, K);

    ln_kernel<<<M, 256>>>(xb, gamma, beta, out);
}

// round 3
// speedup vs baseline: 1.4315x; 1.4315x over previous
#include <cuda_runtime.h>
#include <mma.h>

using namespace nvcuda;

#define B_  4
#define T_  2048
#define D_  1024
#define H_  16
#define DKH 64

// ---------------- scratch (static device globals; no runtime alloc) --------
__device__ float g_qh[(size_t)B_ * T_ * D_];
__device__ float g_kh[(size_t)B_ * T_ * D_];
__device__ float g_vh[(size_t)B_ * T_ * D_];
__device__ float g_ao[(size_t)B_ * T_ * D_];
__device__ float g_x [(size_t)B_ * T_ * D_];
__device__ unsigned long long g_maskp[(size_t)B_ * T_ * (T_ / 64)];  // 2MB

// ---------------- cp.async helpers -----------------------------------------
__device__ __forceinline__ void cp_async16(void* smem, const void* gmem) {
    unsigned s = (unsigned)__cvta_generic_to_shared(smem);
    asm volatile("cp.async.cg.shared.global [%0], [%1], 16;\n" :: "r"(s), "l"(gmem));
}
__device__ __forceinline__ void cp_async8(void* smem, const void* gmem) {
    unsigned s = (unsigned)__cvta_generic_to_shared(smem);
    asm volatile("cp.async.ca.shared.global [%0], [%1], 8;\n" :: "r"(s), "l"(gmem));
}
__device__ __forceinline__ void cp_commit() {
    asm volatile("cp.async.commit_group;\n");
}
template<int N>
__device__ __forceinline__ void cp_wait() {
    asm volatile("cp.async.wait_group %0;\n" :: "n"(N));
}

// ---------------- mask bit-pack: one warp per 64-bit word -------------------
__global__ void pack_mask_kernel(const int* __restrict__ mask,
                                 unsigned long long* __restrict__ mp) {
    const int gw   = (blockIdx.x * blockDim.x + threadIdx.x) >> 5;
    const int lane = threadIdx.x & 31;
    const int* src = mask + (size_t)gw * 64;
    int v0 = src[lane];
    int v1 = src[lane + 32];
    unsigned lo = __ballot_sync(0xffffffffu, v0 != 0);
    unsigned hi = __ballot_sync(0xffffffffu, v1 != 0);
    if (lane == 0) mp[gw] = ((unsigned long long)hi << 32) | lo;
}

// ---------------- tf32 WMMA GEMM v2: C = A@W + bias (+res) ------------------
// BM=128, BN=128, BK=32, 2-stage cp.async, 256 threads, 8 warps (2x4, 64x32)
template<bool HAS_RES>
__global__ __launch_bounds__(256, 2)
void gemm2_kernel(const float* __restrict__ A,
                  const float* __restrict__ W,
                  const float* __restrict__ bias,
                  const float* __restrict__ res,
                  float* __restrict__ C,
                  int M, int N, int K) {
    constexpr int BM = 128, BN = 128, BK = 32;
    constexpr int LDA = 36, LDB = 132, LDC = 132;
    constexpr int ASZ = BM * LDA;   // 4608 floats / stage
    constexpr int BSZ = BK * LDB;   // 4224 floats / stage

    extern __shared__ float sm[];
    float* sA = sm;             // 2 stages
    float* sB = sm + 2 * ASZ;   // 2 stages
    float* Cs = sm;             // epilogue reuse (needs 128*132=16896 <= 17664)

    const int tid  = threadIdx.x;
    const int warp = tid >> 5;
    const int wr   = warp & 1;      // row half (64 rows)
    const int wc   = warp >> 1;     // 0..3 (32-col blocks)
    const int m0   = blockIdx.y * BM;
    const int n0   = blockIdx.x * BN;

    wmma::fragment<wmma::accumulator, 16, 16, 8, float> acc[4][2];
    #pragma unroll
    for (int i = 0; i < 4; i++)
        #pragma unroll
        for (int j = 0; j < 2; j++)
            wmma::fill_fragment(acc[i][j], 0.0f);

    auto load_tile = [&](int k0, int p) {
        float* a = sA + p * ASZ;
        float* b = sB + p * BSZ;
        #pragma unroll
        for (int i = 0; i < 4; i++) {            // A: 128x32 = 1024 float4
            int idx = tid + i * 256;
            int r = idx >> 3, c4 = idx & 7;
            cp_async16(a + r * LDA + c4 * 4, A + (size_t)(m0 + r) * K + k0 + c4 * 4);
        }
        #pragma unroll
        for (int i = 0; i < 4; i++) {            // B: 32x128 = 1024 float4
            int idx = tid + i * 256;
            int r = idx >> 5, c4 = idx & 31;
            cp_async16(b + r * LDB + c4 * 4, W + (size_t)(k0 + r) * N + n0 + c4 * 4);
        }
        cp_commit();
    };

    const int nIter = K / BK;
    load_tile(0, 0);

    for (int it = 0; it < nIter; it++) {
        const int p = it & 1;
        if (it + 1 < nIter) {
            load_tile((it + 1) * BK, p ^ 1);
            cp_wait<1>();
        } else {
            cp_wait<0>();
        }
        __syncthreads();

        const float* a = sA + p * ASZ;
        const float* b = sB + p * BSZ;
        #pragma unroll
        for (int kk = 0; kk < BK / 8; kk++) {
            wmma::fragment<wmma::matrix_a, 16, 16, 8, wmma::precision::tf32, wmma::row_major> af[4];
            wmma::fragment<wmma::matrix_b, 16, 16, 8, wmma::precision::tf32, wmma::row_major> bf[2];
            #pragma unroll
            for (int i = 0; i < 4; i++)
                wmma::load_matrix_sync(af[i], a + (wr * 64 + i * 16) * LDA + kk * 8, LDA);
            #pragma unroll
            for (int j = 0; j < 2; j++)
                wmma::load_matrix_sync(bf[j], b + (kk * 8) * LDB + wc * 32 + j * 16, LDB);
            #pragma unroll
            for (int i = 0; i < 4; i++)
                #pragma unroll
                for (int j = 0; j < 2; j++)
                    wmma::mma_sync(acc[i][j], af[i], bf[j], acc[i][j]);
        }
        __syncthreads();
    }

    // epilogue via smem
    #pragma unroll
    for (int i = 0; i < 4; i++)
        #pragma unroll
        for (int j = 0; j < 2; j++)
            wmma::store_matrix_sync(Cs + (wr * 64 + i * 16) * LDC + wc * 32 + j * 16,
                                    acc[i][j], LDC, wmma::mem_row_major);
    __syncthreads();

    #pragma unroll
    for (int i = 0; i < 16; i++) {   // 128x128 floats = 4096 float4  (FIXED: was 8)
        int idx = tid + i * 256;
        int r = idx >> 5, c4 = idx & 31;
        const int c = c4 * 4;
        float4 bb = *(const float4*)(bias + n0 + c);
        float4 v;
        v.x = Cs[r * LDC + c + 0] + bb.x;
        v.y = Cs[r * LDC + c + 1] + bb.y;
        v.z = Cs[r * LDC + c + 2] + bb.z;
        v.w = Cs[r * LDC + c + 3] + bb.w;
        if (HAS_RES) {
            float4 rr = *(const float4*)(res + (size_t)(m0 + r) * N + n0 + c);
            v.x += rr.x; v.y += rr.y; v.z += rr.z; v.w += rr.w;
        }
        *(float4*)(C + (size_t)(m0 + r) * N + n0 + c) = v;
    }
}

// ---------------- flash attention v2 ----------------------------------------
// 256 threads (8 warps), 128-row Q tile, 64-key tiles, double-buffered cp.async
// grid (T/128, H, B); warp w owns output rows w*16..w*16+15
__global__ __launch_bounds__(256, 1)
void attn2_kernel(const float* __restrict__ Qh,
                  const float* __restrict__ Kh,
                  const float* __restrict__ Vh,
                  const unsigned long long* __restrict__ maskp,
                  float* __restrict__ Out) {
    constexpr int QR = 128, KT = 64, LD = 72;
    extern __shared__ char smraw[];
    unsigned long long* Mp = (unsigned long long*)smraw;            // 2 x 128
    float* Qs     = (float*)(smraw + 2 * QR * 8);
    float* Ks     = Qs + QR * LD;          // 2 stages of 64*LD
    float* Vs     = Ks + 2 * KT * LD;      // 2 stages of 64*LD
    float* Ss     = Vs + 2 * KT * LD;      // 128*LD
    float* alphaM = Ss + QR * LD;          // 128*16
    float* mrow   = alphaM + QR * 16;      // 128
    float* lrow   = mrow + QR;             // 128

    const int tid  = threadIdx.x;
    const int warp = tid >> 5;
    const int q0   = blockIdx.x * QR;
    const int h    = blockIdx.y;
    const int b    = blockIdx.z;

    const float* Qg = Qh + ((size_t)b * T_ + q0) * D_ + h * DKH;

    // load Q (tf32 round-to-nearest), init stats
    for (int i = tid; i < QR * DKH; i += 256) {
        int r = i >> 6, c = i & 63;
        Qs[r * LD + c] = wmma::__float_to_tf32(__ldg(&Qg[(size_t)r * D_ + c]));
    }
    if (tid < QR) { mrow[tid] = -1e30f; lrow[tid] = 0.0f; }

    wmma::fragment<wmma::accumulator, 16, 16, 8, float> o_frag[4];
    #pragma unroll
    for (int j = 0; j < 4; j++) wmma::fill_fragment(o_frag[j], 0.0f);

    auto load_kv = [&](int kt, int p) {
        const int k0 = kt * KT;
        const float* Kg = Kh + ((size_t)b * T_ + k0) * D_ + h * DKH;
        const float* Vg = Vh + ((size_t)b * T_ + k0) * D_ + h * DKH;
        float* kd = Ks + p * KT * LD;
        float* vd = Vs + p * KT * LD;
        #pragma unroll
        for (int i = 0; i < 4; i++) {       // 64x64 = 1024 float4
            int idx = tid + i * 256;
            int r = idx >> 4, c4 = idx & 15;
            cp_async16(kd + r * LD + c4 * 4, Kg + (size_t)r * D_ + c4 * 4);
            cp_async16(vd + r * LD + c4 * 4, Vg + (size_t)r * D_ + c4 * 4);
        }
        if (tid < QR)
            cp_async8(&Mp[p * QR + tid],
                      &maskp[((size_t)b * T_ + q0 + tid) * (T_ / 64) + kt]);
        cp_commit();
    };

    load_kv(0, 0);
    __syncthreads();   // covers Q/stats init ordering vs first use

    constexpr int NT = T_ / KT;   // 32
    for (int kt = 0; kt < NT; kt++) {
        const int p = kt & 1;
        cp_wait<0>();
        __syncthreads();          // tile kt ready; prev PV done -> buf p^1 free
        if (kt + 1 < NT) load_kv(kt + 1, p ^ 1);

        const float* kd = Ks + p * KT * LD;
        const float* vd = Vs + p * KT * LD;

        // S = Q @ K^T : warp rows [warp*16, +16), 64 cols
        {
            wmma::fragment<wmma::matrix_a, 16, 16, 8, wmma::precision::tf32, wmma::row_major> af;
            wmma::fragment<wmma::matrix_b, 16, 16, 8, wmma::precision::tf32, wmma::col_major> bf;
            wmma::fragment<wmma::accumulator, 16, 16, 8, float> sfr[4];
            #pragma unroll
            for (int j = 0; j < 4; j++) wmma::fill_fragment(sfr[j], 0.0f);
            #pragma unroll
            for (int kk = 0; kk < 8; kk++) {
                wmma::load_matrix_sync(af, Qs + (warp * 16) * LD + kk * 8, LD);
                #pragma unroll
                for (int j = 0; j < 4; j++) {
                    wmma::load_matrix_sync(bf, kd + (j * 16) * LD + kk * 8, LD);
                    wmma::mma_sync(sfr[j], af, bf, sfr[j]);
                }
            }
            #pragma unroll
            for (int j = 0; j < 4; j++)
                wmma::store_matrix_sync(Ss + (warp * 16) * LD + j * 16, sfr[j], LD,
                                        wmma::mem_row_major);
        }
        __syncthreads();

        // masked online softmax: 2 threads per row, packed mask bits
        {
            const int r = tid >> 1, half = tid & 1;
            const int cbase = half * 32;
            const unsigned long long m64 = Mp[p * QR + r];
            float sloc[32];
            float mx = -1e30f;
            #pragma unroll
            for (int c = 0; c < 32; c++) {
                float s = Ss[r * LD + cbase + c];
                s = ((m64 >> (cbase + c)) & 1ull) ? s : -1e30f;
                sloc[c] = s;
                mx = fmaxf(mx, s);
            }
            mx = fmaxf(mx, __shfl_xor_sync(0xffffffffu, mx, 1));
            float mold = mrow[r];
            float mnew = fmaxf(mold, mx);
            float lsum = 0.0f;
            #pragma unroll
            for (int c = 0; c < 32; c++) {
                float pv = (sloc[c] > -1e29f) ? __expf(sloc[c] - mnew) : 0.0f;
                lsum += pv;
                Ss[r * LD + cbase + c] = wmma::__float_to_tf32(pv);
            }
            lsum += __shfl_xor_sync(0xffffffffu, lsum, 1);
            float alpha = __expf(mold - mnew);
            if (half == 0) { mrow[r] = mnew; lrow[r] = lrow[r] * alpha + lsum; }
            #pragma unroll
            for (int j = 0; j < 8; j++)
                alphaM[(r << 4) + half * 8 + j] = alpha;
        }
        __syncthreads();

        // O = O*alpha + P @ V
        {
            wmma::fragment<wmma::accumulator, 16, 16, 8, float> afr;
            wmma::load_matrix_sync(afr, alphaM + warp * 16 * 16, 16, wmma::mem_row_major);
            #pragma unroll
            for (int j = 0; j < 4; j++)
                #pragma unroll
                for (int e = 0; e < afr.num_elements; e++)
                    o_frag[j].x[e] *= afr.x[e];

            wmma::fragment<wmma::matrix_a, 16, 16, 8, wmma::precision::tf32, wmma::row_major> pf;
            wmma::fragment<wmma::matrix_b, 16, 16, 8, wmma::precision::tf32, wmma::row_major> vf;
            #pragma unroll
            for (int kk = 0; kk < 8; kk++) {
                wmma::load_matrix_sync(pf, Ss + (warp * 16) * LD + kk * 8, LD);
                #pragma unroll
                for (int j = 0; j < 4; j++) {
                    wmma::load_matrix_sync(vf, vd + (kk * 8) * LD + j * 16, LD);
                    wmma::mma_sync(o_frag[j], pf, vf, o_frag[j]);
                }
            }
        }
        // no trailing sync: next iteration's wait+sync protects buffers
    }

    // epilogue: O / (l + 1e-15)
    __syncthreads();
    #pragma unroll
    for (int j = 0; j < 4; j++)
        wmma::store_matrix_sync(Ss + (warp * 16) * LD + j * 16, o_frag[j], LD,
                                wmma::mem_row_major);
    __syncthreads();
    for (int i = tid; i < QR * DKH; i += 256) {
        int r = i >> 6, c = i & 63;
        float v = Ss[r * LD + c] / (lrow[r] + 1e-15f);
        Out[((size_t)b * T_ + q0 + r) * D_ + h * DKH + c] = v;
    }
}

// ---------------- LayerNorm over D=1024, one block per row -----------------
__global__ void ln_kernel(const float* __restrict__ X,
                          const float* __restrict__ gamma,
                          const float* __restrict__ beta,
                          float* __restrict__ Out) {
    const int row = blockIdx.x;
    const int tid = threadIdx.x;              // 256 threads, 4 floats each
    const float* x = X + (size_t)row * D_;

    __shared__ float red[8];
    __shared__ float s_mu, s_inv;

    float4 v = ((const float4*)x)[tid];
    float s = v.x + v.y + v.z + v.w;
    #pragma unroll
    for (int o = 16; o > 0; o >>= 1) s += __shfl_xor_sync(0xffffffffu, s, o);
    if ((tid & 31) == 0) red[tid >> 5] = s;
    __syncthreads();
    if (tid == 0) {
        float t = 0.0f;
        #pragma unroll
        for (int i = 0; i < 8; i++) t += red[i];
        s_mu = t * (1.0f / D_);
    }
    __syncthreads();
    const float mu = s_mu;

    float dx = v.x - mu, dy = v.y - mu, dz = v.z - mu, dw = v.w - mu;
    float s2 = dx * dx + dy * dy + dz * dz + dw * dw;
    #pragma unroll
    for (int o = 16; o > 0; o >>= 1) s2 += __shfl_xor_sync(0xffffffffu, s2, o);
    if ((tid & 31) == 0) red[tid >> 5] = s2;
    __syncthreads();
    if (tid == 0) {
        float t = 0.0f;
        #pragma unroll
        for (int i = 0; i < 8; i++) t += red[i];
        s_inv = rsqrtf(t * (1.0f / D_) + 1e-5f);
    }
    __syncthreads();
    const float inv = s_inv;

    const int c = tid * 4;
    float4 g = ((const float4*)(gamma + c))[0];
    float4 bb = ((const float4*)(beta + c))[0];
    float4 o;
    o.x = dx * inv * g.x + bb.x;
    o.y = dy * inv * g.y + bb.y;
    o.z = dz * inv * g.z + bb.z;
    o.w = dw * inv * g.w + bb.w;
    ((float4*)(Out + (size_t)row * D_))[tid] = o;
}

// ---------------- launch ----------------------------------------------------
extern "C" void kernel_launch(void* const* d_in, const int* in_sizes, int n_in,
                              void* d_out, int out_size) {
    const float* q     = (const float*)d_in[0];
    const float* k     = (const float*)d_in[1];
    const float* v     = (const float*)d_in[2];
    const int*   mask  = (const int*)  d_in[3];
    const float* Wq    = (const float*)d_in[4];
    const float* bq    = (const float*)d_in[5];
    const float* Wk    = (const float*)d_in[6];
    const float* bk    = (const float*)d_in[7];
    const float* Wv    = (const float*)d_in[8];
    const float* bv    = (const float*)d_in[9];
    const float* Wo    = (const float*)d_in[10];
    const float* bo    = (const float*)d_in[11];
    const float* gamma = (const float*)d_in[12];
    const float* beta  = (const float*)d_in[13];
    float* out = (float*)d_out;

    float *qh, *kh, *vh, *ao, *xb;
    unsigned long long* mp;
    cudaGetSymbolAddress((void**)&qh, g_qh);
    cudaGetSymbolAddress((void**)&kh, g_kh);
    cudaGetSymbolAddress((void**)&vh, g_vh);
    cudaGetSymbolAddress((void**)&ao, g_ao);
    cudaGetSymbolAddress((void**)&xb, g_x);
    cudaGetSymbolAddress((void**)&mp, g_maskp);

    const int M = B_ * T_;   // 8192
    const int N = D_;        // 1024
    const int K = D_;        // 1024

    // pack mask to bits (one warp per 64-bit word)
    {
        const int words = B_ * T_ * (T_ / 64);          // 262144
        pack_mask_kernel<<<words * 32 / 256, 256>>>(mask, mp);
    }

    const int gemm_smem = (2 * 128 * 36 + 2 * 32 * 132) * 4;   // 70656 B
    cudaFuncSetAttribute(gemm2_kernel<false>,
                         cudaFuncAttributeMaxDynamicSharedMemorySize, gemm_smem);
    cudaFuncSetAttribute(gemm2_kernel<true>,
                         cudaFuncAttributeMaxDynamicSharedMemorySize, gemm_smem);

    dim3 gg(N / 128, M / 128);      // (8, 64)
    gemm2_kernel<false><<<gg, 256, gemm_smem>>>(q, Wq, bq, nullptr, qh, M, N, K);
    gemm2_kernel<false><<<gg, 256, gemm_smem>>>(k, Wk, bk, nullptr, kh, M, N, K);
    gemm2_kernel<false><<<gg, 256, gemm_smem>>>(v, Wv, bv, nullptr, vh, M, N, K);

    const int attn_smem = 2 * 128 * 8 +
        (128 * 72 + 2 * 64 * 72 + 2 * 64 * 72 + 128 * 72 + 128 * 16 + 256) * 4;  // 158720
    cudaFuncSetAttribute(attn2_kernel,
                         cudaFuncAttributeMaxDynamicSharedMemorySize, attn_smem);
    dim3 ga(T_ / 128, H_, B_);      // (16, 16, 4)
    attn2_kernel<<<ga, 256, attn_smem>>>(qh, kh, vh, mp, ao);

    gemm2_kernel<true><<<gg, 256, gemm_smem>>>(ao, Wo, bo, q, xb, M, N, K);

    ln_kernel<<<M, 256>>>(xb, gamma, beta, out);
}

// round 5
// speedup vs baseline: 4.4362x; 3.0990x over previous
#include <cuda_runtime.h>
#include <cuda_fp16.h>
#include <mma.h>
#include <cstdint>

using namespace nvcuda;

#define B_  4
#define T_  2048
#define D_  1024
#define H_  16
#define DKH 64

// ---------------- scratch (static device globals; no runtime alloc) --------
__device__ __half g_qx[(size_t)B_ * T_ * D_];   // fp16 inputs
__device__ __half g_kx[(size_t)B_ * T_ * D_];
__device__ __half g_vx[(size_t)B_ * T_ * D_];
__device__ __half g_wh[4][(size_t)D_ * D_];     // fp16 weights [K,N]
__device__ __half g_qh[(size_t)B_ * T_ * D_];   // fp16 projections
__device__ __half g_kh[(size_t)B_ * T_ * D_];
__device__ __half g_vh[(size_t)B_ * T_ * D_];
__device__ __half g_ao[(size_t)B_ * T_ * D_];   // fp16 attention output
__device__ float  g_x [(size_t)B_ * T_ * D_];   // fp32 pre-LN
__device__ unsigned long long g_maskp[(size_t)B_ * T_ * (T_ / 64)];  // 2MB

// ---------------- cp.async helpers -----------------------------------------
__device__ __forceinline__ void cp_async16(void* smem, const void* gmem) {
    unsigned s = (unsigned)__cvta_generic_to_shared(smem);
    asm volatile("cp.async.cg.shared.global [%0], [%1], 16;\n" :: "r"(s), "l"(gmem));
}
__device__ __forceinline__ void cp_async8(void* smem, const void* gmem) {
    unsigned s = (unsigned)__cvta_generic_to_shared(smem);
    asm volatile("cp.async.ca.shared.global [%0], [%1], 8;\n" :: "r"(s), "l"(gmem));
}
__device__ __forceinline__ void cp_commit() {
    asm volatile("cp.async.commit_group;\n");
}
template<int N>
__device__ __forceinline__ void cp_wait() {
    asm volatile("cp.async.wait_group %0;\n" :: "n"(N));
}

// ---------------- mask bit-pack: one warp per 64-bit word -------------------
__global__ void pack_mask_kernel(const int* __restrict__ mask,
                                 unsigned long long* __restrict__ mp) {
    const int gw   = (blockIdx.x * blockDim.x + threadIdx.x) >> 5;
    const int lane = threadIdx.x & 31;
    const int* src = mask + (size_t)gw * 64;
    int v0 = src[lane];
    int v1 = src[lane + 32];
    unsigned lo = __ballot_sync(0xffffffffu, v0 != 0);
    unsigned hi = __ballot_sync(0xffffffffu, v1 != 0);
    if (lane == 0) mp[gw] = ((unsigned long long)hi << 32) | lo;
}

// ---------------- fp32 -> fp16 convert --------------------------------------
__global__ void f2h_kernel(const float* __restrict__ in,
                           __half* __restrict__ out, int n4) {
    int i = blockIdx.x * blockDim.x + threadIdx.x;
    if (i >= n4) return;
    float4 v = ((const float4*)in)[i];
    __half2 h0 = __floats2half2_rn(v.x, v.y);
    __half2 h1 = __floats2half2_rn(v.z, v.w);
    ((__half2*)out)[2 * i + 0] = h0;
    ((__half2*)out)[2 * i + 1] = h1;
}

// ---------------- fp16 WMMA GEMM: C = A@W + bias (+res) ---------------------
// BM=128, BN=128, BK=64, 2-stage cp.async, 256 threads, 8 warps (2x4, 64x32)
// OUT_HALF: write half (projections). else: fp32 out + fp32 residual.
template<bool OUT_HALF>
__global__ __launch_bounds__(256, 2)
void gemm4_kernel(const __half* __restrict__ A,
                  const __half* __restrict__ W,
                  const float* __restrict__ bias,
                  const float* __restrict__ res,
                  void* __restrict__ Cout,
                  int M, int N, int K) {
    constexpr int BM = 128, BN = 128, BK = 64;
    constexpr int LDA = 72, LDB = 136, LDC = 132;
    constexpr int ASZ = BM * LDA;   // 9216 halves / stage
    constexpr int BSZ = BK * LDB;   // 8704 halves / stage

    extern __shared__ char smraw[];
    __half* sA = (__half*)smraw;          // 2 stages
    __half* sB = sA + 2 * ASZ;            // 2 stages
    float*  Cs = (float*)smraw;           // epilogue reuse: 128*132*4 = 67584

    const int tid  = threadIdx.x;
    const int warp = tid >> 5;
    const int wr   = warp & 1;      // row half (64 rows)
    const int wc   = warp >> 1;     // 0..3 (32-col blocks)
    const int m0   = blockIdx.y * BM;
    const int n0   = blockIdx.x * BN;

    wmma::fragment<wmma::accumulator, 16, 16, 16, float> acc[4][2];
    #pragma unroll
    for (int i = 0; i < 4; i++)
        #pragma unroll
        for (int j = 0; j < 2; j++)
            wmma::fill_fragment(acc[i][j], 0.0f);

    auto load_tile = [&](int k0, int p) {
        __half* a = sA + p * ASZ;
        __half* b = sB + p * BSZ;
        #pragma unroll
        for (int i = 0; i < 4; i++) {            // A: 128x64 halves = 1024 chunks
            int idx = tid + i * 256;
            int r = idx >> 3, c8 = idx & 7;
            cp_async16(a + r * LDA + c8 * 8, A + (size_t)(m0 + r) * K + k0 + c8 * 8);
        }
        #pragma unroll
        for (int i = 0; i < 4; i++) {            // B: 64x128 halves = 1024 chunks
            int idx = tid + i * 256;
            int r = idx >> 4, c8 = idx & 15;
            cp_async16(b + r * LDB + c8 * 8, W + (size_t)(k0 + r) * N + n0 + c8 * 8);
        }
        cp_commit();
    };

    const int nIter = K / BK;       // 16
    load_tile(0, 0);

    for (int it = 0; it < nIter; it++) {
        const int p = it & 1;
        if (it + 1 < nIter) {
            load_tile((it + 1) * BK, p ^ 1);
            cp_wait<1>();
        } else {
            cp_wait<0>();
        }
        __syncthreads();

        const __half* a = sA + p * ASZ;
        const __half* b = sB + p * BSZ;
        #pragma unroll
        for (int kk = 0; kk < BK / 16; kk++) {
            wmma::fragment<wmma::matrix_a, 16, 16, 16, __half, wmma::row_major> af[4];
            wmma::fragment<wmma::matrix_b, 16, 16, 16, __half, wmma::row_major> bf[2];
            #pragma unroll
            for (int i = 0; i < 4; i++)
                wmma::load_matrix_sync(af[i], a + (wr * 64 + i * 16) * LDA + kk * 16, LDA);
            #pragma unroll
            for (int j = 0; j < 2; j++)
                wmma::load_matrix_sync(bf[j], b + (kk * 16) * LDB + wc * 32 + j * 16, LDB);
            #pragma unroll
            for (int i = 0; i < 4; i++)
                #pragma unroll
                for (int j = 0; j < 2; j++)
                    wmma::mma_sync(acc[i][j], af[i], bf[j], acc[i][j]);
        }
        __syncthreads();
    }

    // epilogue via smem
    #pragma unroll
    for (int i = 0; i < 4; i++)
        #pragma unroll
        for (int j = 0; j < 2; j++)
            wmma::store_matrix_sync(Cs + (wr * 64 + i * 16) * LDC + wc * 32 + j * 16,
                                    acc[i][j], LDC, wmma::mem_row_major);
    __syncthreads();

    #pragma unroll
    for (int i = 0; i < 16; i++) {   // 128x128 = 4096 float4-groups
        int idx = tid + i * 256;
        int r = idx >> 5, c4 = idx & 31;
        const int c = c4 * 4;
        float4 bb = *(const float4*)(bias + n0 + c);
        float vx = Cs[r * LDC + c + 0] + bb.x;
        float vy = Cs[r * LDC + c + 1] + bb.y;
        float vz = Cs[r * LDC + c + 2] + bb.z;
        float vw = Cs[r * LDC + c + 3] + bb.w;
        if (OUT_HALF) {
            __half2* dst = (__half2*)((__half*)Cout + (size_t)(m0 + r) * N + n0 + c);
            dst[0] = __floats2half2_rn(vx, vy);
            dst[1] = __floats2half2_rn(vz, vw);
        } else {
            float4 rr = *(const float4*)(res + (size_t)(m0 + r) * N + n0 + c);
            float4 o;
            o.x = vx + rr.x; o.y = vy + rr.y; o.z = vz + rr.z; o.w = vw + rr.w;
            *(float4*)((float*)Cout + (size_t)(m0 + r) * N + n0 + c) = o;
        }
    }
}

// ---------------- flash attention v3 (fp16 operands, fp32 softmax/accum) ----
// 256 threads (8 warps), 128-row Q tile, 64-key tiles, double-buffered cp.async
__global__ __launch_bounds__(256, 1)
void attn3_kernel(const __half* __restrict__ Qh,
                  const __half* __restrict__ Kh,
                  const __half* __restrict__ Vh,
                  const unsigned long long* __restrict__ maskp,
                  __half* __restrict__ Out) {
    constexpr int QR = 128, KT = 64, LD = 72;
    extern __shared__ char smraw[];
    // floats first, then halves; every section a multiple of 16B
    unsigned long long* Mp = (unsigned long long*)smraw;        // 2*128*8 = 2048
    float* Ssf    = (float*)(smraw + 2048);                     // 128*72*4 = 36864
    float* alphaM = Ssf + QR * LD;                              // 128*16*4 = 8192
    float* mrow   = alphaM + QR * 16;                           // 512
    float* lrow   = mrow + QR;                                  // 512
    __half* Qs    = (__half*)(lrow + QR);                       // 128*72*2 = 18432
    __half* Ks    = Qs + QR * LD;                               // 2*64*72*2 = 18432
    __half* Vs    = Ks + 2 * KT * LD;                           // 18432
    __half* Ps    = Vs + 2 * KT * LD;                           // 128*72*2 = 18432

    const int tid  = threadIdx.x;
    const int warp = tid >> 5;
    const int q0   = blockIdx.x * QR;
    const int h    = blockIdx.y;
    const int b    = blockIdx.z;

    const __half* Qg = Qh + ((size_t)b * T_ + q0) * D_ + h * DKH;

    // load Q via cp.async (128x64 halves = 1024 16B chunks)
    #pragma unroll
    for (int i = 0; i < 4; i++) {
        int idx = tid + i * 256;
        int r = idx >> 3, c8 = idx & 7;
        cp_async16(Qs + r * LD + c8 * 8, Qg + (size_t)r * D_ + c8 * 8);
    }
    cp_commit();
    if (tid < QR) { mrow[tid] = -1e30f; lrow[tid] = 0.0f; }

    wmma::fragment<wmma::accumulator, 16, 16, 16, float> o_frag[4];
    #pragma unroll
    for (int j = 0; j < 4; j++) wmma::fill_fragment(o_frag[j], 0.0f);

    auto load_kv = [&](int kt, int p) {
        const int k0 = kt * KT;
        const __half* Kg = Kh + ((size_t)b * T_ + k0) * D_ + h * DKH;
        const __half* Vg = Vh + ((size_t)b * T_ + k0) * D_ + h * DKH;
        __half* kd = Ks + p * KT * LD;
        __half* vd = Vs + p * KT * LD;
        #pragma unroll
        for (int i = 0; i < 2; i++) {       // 64x64 halves = 512 chunks each
            int idx = tid + i * 256;
            int r = idx >> 3, c8 = idx & 7;
            cp_async16(kd + r * LD + c8 * 8, Kg + (size_t)r * D_ + c8 * 8);
            cp_async16(vd + r * LD + c8 * 8, Vg + (size_t)r * D_ + c8 * 8);
        }
        if (tid < QR)
            cp_async8(&Mp[p * QR + tid],
                      &maskp[((size_t)b * T_ + q0 + tid) * (T_ / 64) + kt]);
        cp_commit();
    };

    load_kv(0, 0);
    __syncthreads();

    constexpr int NT = T_ / KT;   // 32
    for (int kt = 0; kt < NT; kt++) {
        const int p = kt & 1;
        cp_wait<0>();
        __syncthreads();          // tile kt ready; prev PV done -> other buf free
        if (kt + 1 < NT) load_kv(kt + 1, p ^ 1);

        const __half* kd = Ks + p * KT * LD;
        const __half* vd = Vs + p * KT * LD;

        // S = Q @ K^T : warp rows [warp*16, +16), 64 cols, k=64 (4 steps)
        {
            wmma::fragment<wmma::matrix_a, 16, 16, 16, __half, wmma::row_major> af;
            wmma::fragment<wmma::matrix_b, 16, 16, 16, __half, wmma::col_major> bf;
            wmma::fragment<wmma::accumulator, 16, 16, 16, float> sfr[4];
            #pragma unroll
            for (int j = 0; j < 4; j++) wmma::fill_fragment(sfr[j], 0.0f);
            #pragma unroll
            for (int kk = 0; kk < 4; kk++) {
                wmma::load_matrix_sync(af, Qs + (warp * 16) * LD + kk * 16, LD);
                #pragma unroll
                for (int j = 0; j < 4; j++) {
                    wmma::load_matrix_sync(bf, kd + (j * 16) * LD + kk * 16, LD);
                    wmma::mma_sync(sfr[j], af, bf, sfr[j]);
                }
            }
            #pragma unroll
            for (int j = 0; j < 4; j++)
                wmma::store_matrix_sync(Ssf + (warp * 16) * LD + j * 16, sfr[j], LD,
                                        wmma::mem_row_major);
        }
        __syncthreads();

        // masked online softmax: 2 threads per row, packed mask bits
        {
            const int r = tid >> 1, half = tid & 1;
            const int cbase = half * 32;
            const unsigned long long m64 = Mp[p * QR + r];
            float sloc[32];
            float mx = -1e30f;
            #pragma unroll
            for (int c = 0; c < 32; c++) {
                float s = Ssf[r * LD + cbase + c];
                s = ((m64 >> (cbase + c)) & 1ull) ? s : -1e30f;
                sloc[c] = s;
                mx = fmaxf(mx, s);
            }
            mx = fmaxf(mx, __shfl_xor_sync(0xffffffffu, mx, 1));
            float mold = mrow[r];
            float mnew = fmaxf(mold, mx);
            float lsum = 0.0f;
            #pragma unroll
            for (int c = 0; c < 32; c += 2) {
                float p0 = (sloc[c]     > -1e29f) ? __expf(sloc[c]     - mnew) : 0.0f;
                float p1 = (sloc[c + 1] > -1e29f) ? __expf(sloc[c + 1] - mnew) : 0.0f;
                lsum += p0 + p1;
                *(__half2*)(Ps + r * LD + cbase + c) = __floats2half2_rn(p0, p1);
            }
            lsum += __shfl_xor_sync(0xffffffffu, lsum, 1);
            float alpha = __expf(mold - mnew);
            if (half == 0) { mrow[r] = mnew; lrow[r] = lrow[r] * alpha + lsum; }
            #pragma unroll
            for (int j = 0; j < 8; j++)
                alphaM[(r << 4) + half * 8 + j] = alpha;
        }
        __syncthreads();

        // O = O*alpha + P @ V
        {
            wmma::fragment<wmma::accumulator, 16, 16, 16, float> afr;
            wmma::load_matrix_sync(afr, alphaM + warp * 16 * 16, 16, wmma::mem_row_major);
            #pragma unroll
            for (int j = 0; j < 4; j++)
                #pragma unroll
                for (int e = 0; e < afr.num_elements; e++)
                    o_frag[j].x[e] *= afr.x[e];

            wmma::fragment<wmma::matrix_a, 16, 16, 16, __half, wmma::row_major> pf;
            wmma::fragment<wmma::matrix_b, 16, 16, 16, __half, wmma::row_major> vf;
            #pragma unroll
            for (int kk = 0; kk < 4; kk++) {
                wmma::load_matrix_sync(pf, Ps + (warp * 16) * LD + kk * 16, LD);
                #pragma unroll
                for (int j = 0; j < 4; j++) {
                    wmma::load_matrix_sync(vf, vd + (kk * 16) * LD + j * 16, LD);
                    wmma::mma_sync(o_frag[j], pf, vf, o_frag[j]);
                }
            }
        }
        // next iteration's wait+sync protects buffers
    }

    // epilogue: O / (l + 1e-15), write half
    __syncthreads();
    #pragma unroll
    for (int j = 0; j < 4; j++)
        wmma::store_matrix_sync(Ssf + (warp * 16) * LD + j * 16, o_frag[j], LD,
                                wmma::mem_row_major);
    __syncthreads();
    for (int i = tid; i < QR * DKH / 2; i += 256) {
        int r = i >> 5, c = (i & 31) * 2;
        float inv = 1.0f / (lrow[r] + 1e-15f);
        float v0 = Ssf[r * LD + c] * inv;
        float v1 = Ssf[r * LD + c + 1] * inv;
        *(__half2*)(Out + ((size_t)b * T_ + q0 + r) * D_ + h * DKH + c) =
            __floats2half2_rn(v0, v1);
    }
}

// ---------------- LayerNorm over D=1024, one block per row -----------------
__global__ void ln_kernel(const float* __restrict__ X,
                          const float* __restrict__ gamma,
                          const float* __restrict__ beta,
                          float* __restrict__ Out) {
    const int row = blockIdx.x;
    const int tid = threadIdx.x;
    const float* x = X + (size_t)row * D_;

    __shared__ float red[8];
    __shared__ float s_mu, s_inv;

    float4 v = ((const float4*)x)[tid];
    float s = v.x + v.y + v.z + v.w;
    #pragma unroll
    for (int o = 16; o > 0; o >>= 1) s += __shfl_xor_sync(0xffffffffu, s, o);
    if ((tid & 31) == 0) red[tid >> 5] = s;
    __syncthreads();
    if (tid == 0) {
        float t = 0.0f;
        #pragma unroll
        for (int i = 0; i < 8; i++) t += red[i];
        s_mu = t * (1.0f / D_);
    }
    __syncthreads();
    const float mu = s_mu;

    float dx = v.x - mu, dy = v.y - mu, dz = v.z - mu, dw = v.w - mu;
    float s2 = dx * dx + dy * dy + dz * dz + dw * dw;
    #pragma unroll
    for (int o = 16; o > 0; o >>= 1) s2 += __shfl_xor_sync(0xffffffffu, s2, o);
    if ((tid & 31) == 0) red[tid >> 5] = s2;
    __syncthreads();
    if (tid == 0) {
        float t = 0.0f;
        #pragma unroll
        for (int i = 0; i < 8; i++) t += red[i];
        s_inv = rsqrtf(t * (1.0f / D_) + 1e-5f);
    }
    __syncthreads();
    const float inv = s_inv;

    const int c = tid * 4;
    float4 g = ((const float4*)(gamma + c))[0];
    float4 bb = ((const float4*)(beta + c))[0];
    float4 o;
    o.x = dx * inv * g.x + bb.x;
    o.y = dy * inv * g.y + bb.y;
    o.z = dz * inv * g.z + bb.z;
    o.w = dw * inv * g.w + bb.w;
    ((float4*)(Out + (size_t)row * D_))[tid] = o;
}

// ---------------- launch ----------------------------------------------------
extern "C" void kernel_launch(void* const* d_in, const int* in_sizes, int n_in,
                              void* d_out, int out_size) {
    const float* q     = (const float*)d_in[0];
    const float* k     = (const float*)d_in[1];
    const float* v     = (const float*)d_in[2];
    const int*   mask  = (const int*)  d_in[3];
    const float* Wq    = (const float*)d_in[4];
    const float* bq    = (const float*)d_in[5];
    const float* Wk    = (const float*)d_in[6];
    const float* bk    = (const float*)d_in[7];
    const float* Wv    = (const float*)d_in[8];
    const float* bv    = (const float*)d_in[9];
    const float* Wo    = (const float*)d_in[10];
    const float* bo    = (const float*)d_in[11];
    const float* gamma = (const float*)d_in[12];
    const float* beta  = (const float*)d_in[13];
    float* out = (float*)d_out;

    __half *qx, *kx, *vx, *wh, *qh, *kh, *vh, *ao;
    float *xb;
    unsigned long long* mp;
    cudaGetSymbolAddress((void**)&qx, g_qx);
    cudaGetSymbolAddress((void**)&kx, g_kx);
    cudaGetSymbolAddress((void**)&vx, g_vx);
    cudaGetSymbolAddress((void**)&wh, g_wh);
    cudaGetSymbolAddress((void**)&qh, g_qh);
    cudaGetSymbolAddress((void**)&kh, g_kh);
    cudaGetSymbolAddress((void**)&vh, g_vh);
    cudaGetSymbolAddress((void**)&ao, g_ao);
    cudaGetSymbolAddress((void**)&xb, g_x);
    cudaGetSymbolAddress((void**)&mp, g_maskp);

    __half* wq_h = wh;
    __half* wk_h = wh + (size_t)D_ * D_;
    __half* wv_h = wh + 2 * (size_t)D_ * D_;
    __half* wo_h = wh + 3 * (size_t)D_ * D_;

    const int M = B_ * T_;   // 8192
    const int N = D_;        // 1024
    const int K = D_;        // 1024

    // pack mask to bits
    {
        const int words = B_ * T_ * (T_ / 64);
        pack_mask_kernel<<<words * 32 / 256, 256>>>(mask, mp);
    }

    // fp32 -> fp16 conversions (RTN)
    {
        const int n4a = (B_ * T_ * D_) / 4;   // 2,097,152
        f2h_kernel<<<n4a / 256, 256>>>(q, qx, n4a);
        f2h_kernel<<<n4a / 256, 256>>>(k, kx, n4a);
        f2h_kernel<<<n4a / 256, 256>>>(v, vx, n4a);
        const int n4w = (D_ * D_) / 4;        // 262,144
        f2h_kernel<<<n4w / 256, 256>>>(Wq, wq_h, n4w);
        f2h_kernel<<<n4w / 256, 256>>>(Wk, wk_h, n4w);
        f2h_kernel<<<n4w / 256, 256>>>(Wv, wv_h, n4w);
        f2h_kernel<<<n4w / 256, 256>>>(Wo, wo_h, n4w);
    }

    // fp16 WMMA GEMMs
    const int gemm_smem = 2 * (128 * 72 + 64 * 136) * 2;   // 71680 B
    cudaFuncSetAttribute(gemm4_kernel<true>,
                         cudaFuncAttributeMaxDynamicSharedMemorySize, gemm_smem);
    cudaFuncSetAttribute(gemm4_kernel<false>,
                         cudaFuncAttributeMaxDynamicSharedMemorySize, gemm_smem);

    dim3 gg(N / 128, M / 128);      // (8, 64)
    gemm4_kernel<true><<<gg, 256, gemm_smem>>>(qx, wq_h, bq, nullptr, qh, M, N, K);
    gemm4_kernel<true><<<gg, 256, gemm_smem>>>(kx, wk_h, bk, nullptr, kh, M, N, K);
    gemm4_kernel<true><<<gg, 256, gemm_smem>>>(vx, wv_h, bv, nullptr, vh, M, N, K);

    const int attn_smem = 2048 + 36864 + 8192 + 512 + 512
                        + 18432 + 18432 + 18432 + 18432;   // 121856 B
    cudaFuncSetAttribute(attn3_kernel,
                         cudaFuncAttributeMaxDynamicSharedMemorySize, attn_smem);
    dim3 ga(T_ / 128, H_, B_);      // (16, 16, 4)
    attn3_kernel<<<ga, 256, attn_smem>>>(qh, kh, vh, mp, ao);

    gemm4_kernel<false><<<gg, 256, gemm_smem>>>(ao, wo_h, bo, q, xb, M, N, K);

    ln_kernel<<<M, 256>>>(xb, gamma, beta, out);
}

// round 6
// speedup vs baseline: 4.5731x; 1.0308x over previous
#include <cuda_runtime.h>
#include <cuda_fp16.h>
#include <mma.h>
#include <cstdint>

using namespace nvcuda;

#define B_  4
#define T_  2048
#define D_  1024
#define H_  16
#define DKH 64

// ---------------- scratch (static device globals; no runtime alloc) --------
__device__ __half g_qx[(size_t)B_ * T_ * D_];   // fp16 inputs
__device__ __half g_kx[(size_t)B_ * T_ * D_];
__device__ __half g_vx[(size_t)B_ * T_ * D_];
__device__ __half g_wh[4][(size_t)D_ * D_];     // fp16 weights [K,N]
__device__ __half g_qh[(size_t)B_ * T_ * D_];   // fp16 projections
__device__ __half g_kh[(size_t)B_ * T_ * D_];
__device__ __half g_vh[(size_t)B_ * T_ * D_];
__device__ __half g_ao[(size_t)B_ * T_ * D_];   // fp16 attention output
__device__ float  g_x [(size_t)B_ * T_ * D_];   // fp32 pre-LN
__device__ unsigned long long g_maskp[(size_t)B_ * T_ * (T_ / 64)];  // 2MB

// ---------------- cp.async helpers -----------------------------------------
__device__ __forceinline__ void cp_async16(void* smem, const void* gmem) {
    unsigned s = (unsigned)__cvta_generic_to_shared(smem);
    asm volatile("cp.async.cg.shared.global [%0], [%1], 16;\n" :: "r"(s), "l"(gmem));
}
__device__ __forceinline__ void cp_async8(void* smem, const void* gmem) {
    unsigned s = (unsigned)__cvta_generic_to_shared(smem);
    asm volatile("cp.async.ca.shared.global [%0], [%1], 8;\n" :: "r"(s), "l"(gmem));
}
__device__ __forceinline__ void cp_commit() {
    asm volatile("cp.async.commit_group;\n");
}
template<int N>
__device__ __forceinline__ void cp_wait() {
    asm volatile("cp.async.wait_group %0;\n" :: "n"(N));
}

// ---------------- mask bit-pack: one warp per 64-bit word -------------------
__global__ void pack_mask_kernel(const int* __restrict__ mask,
                                 unsigned long long* __restrict__ mp) {
    const int gw   = (blockIdx.x * blockDim.x + threadIdx.x) >> 5;
    const int lane = threadIdx.x & 31;
    const int* src = mask + (size_t)gw * 64;
    int v0 = src[lane];
    int v1 = src[lane + 32];
    unsigned lo = __ballot_sync(0xffffffffu, v0 != 0);
    unsigned hi = __ballot_sync(0xffffffffu, v1 != 0);
    if (lane == 0) mp[gw] = ((unsigned long long)hi << 32) | lo;
}

// ---------------- fp32 -> fp16 convert (3-way batched) ----------------------
__global__ void f2h3_kernel(const float* __restrict__ s0, __half* __restrict__ d0,
                            const float* __restrict__ s1, __half* __restrict__ d1,
                            const float* __restrict__ s2, __half* __restrict__ d2,
                            int n4) {
    int i = blockIdx.x * blockDim.x + threadIdx.x;
    if (i >= n4) return;
    const float* in = (blockIdx.y == 0) ? s0 : (blockIdx.y == 1) ? s1 : s2;
    __half* out     = (blockIdx.y == 0) ? d0 : (blockIdx.y == 1) ? d1 : d2;
    float4 v = ((const float4*)in)[i];
    ((__half2*)out)[2 * i + 0] = __floats2half2_rn(v.x, v.y);
    ((__half2*)out)[2 * i + 1] = __floats2half2_rn(v.z, v.w);
}
__global__ void f2h4_kernel(const float* __restrict__ s0, const float* __restrict__ s1,
                            const float* __restrict__ s2, const float* __restrict__ s3,
                            __half* __restrict__ dst, int n4) {
    int i = blockIdx.x * blockDim.x + threadIdx.x;
    if (i >= n4) return;
    const float* in = (blockIdx.y == 0) ? s0 : (blockIdx.y == 1) ? s1
                    : (blockIdx.y == 2) ? s2 : s3;
    __half* out = dst + (size_t)blockIdx.y * D_ * D_;
    float4 v = ((const float4*)in)[i];
    ((__half2*)out)[2 * i + 0] = __floats2half2_rn(v.x, v.y);
    ((__half2*)out)[2 * i + 1] = __floats2half2_rn(v.z, v.w);
}

// ---------------- fp16 WMMA GEMM v5: 64x64 warp tiles, 3-stage --------------
// BM=128, BN=128, BK=64, 128 threads (4 warps: 2x2 of 64x64)
template<bool OUT_HALF>
__global__ __launch_bounds__(128, 2)
void gemm5_kernel(const __half* __restrict__ A,
                  const __half* __restrict__ W,
                  const float* __restrict__ bias,
                  const float* __restrict__ res,
                  void* __restrict__ Cout,
                  int M, int N, int K) {
    constexpr int BM = 128, BN = 128, BK = 64;
    constexpr int LDA = 72, LDB = 136, LDC = 132;
    constexpr int ASZ = BM * LDA;   // 9216 halves / stage
    constexpr int BSZ = BK * LDB;   // 8704 halves / stage
    constexpr int NSTAGE = 3;

    extern __shared__ char smraw[];
    __half* sA = (__half*)smraw;            // 3 stages
    __half* sB = sA + NSTAGE * ASZ;         // 3 stages
    float*  Cs = (float*)smraw;             // epilogue reuse (67584B <= 107520B)

    const int tid  = threadIdx.x;
    const int warp = tid >> 5;
    const int wr   = warp & 1;      // 64-row half
    const int wc   = warp >> 1;     // 64-col half
    const int m0   = blockIdx.y * BM;
    const int n0   = blockIdx.x * BN;

    wmma::fragment<wmma::accumulator, 16, 16, 16, float> acc[4][4];
    #pragma unroll
    for (int i = 0; i < 4; i++)
        #pragma unroll
        for (int j = 0; j < 4; j++)
            wmma::fill_fragment(acc[i][j], 0.0f);

    auto load_tile = [&](int k0, int p) {
        __half* a = sA + p * ASZ;
        __half* b = sB + p * BSZ;
        #pragma unroll
        for (int i = 0; i < 8; i++) {            // A: 128x64 halves = 1024 chunks
            int idx = tid + i * 128;
            int r = idx >> 3, c8 = idx & 7;
            cp_async16(a + r * LDA + c8 * 8, A + (size_t)(m0 + r) * K + k0 + c8 * 8);
        }
        #pragma unroll
        for (int i = 0; i < 8; i++) {            // B: 64x128 halves = 1024 chunks
            int idx = tid + i * 128;
            int r = idx >> 4, c8 = idx & 15;
            cp_async16(b + r * LDB + c8 * 8, W + (size_t)(k0 + r) * N + n0 + c8 * 8);
        }
        cp_commit();
    };

    const int nIter = K / BK;       // 16
    load_tile(0, 0);
    load_tile(BK, 1);

    for (int it = 0; it < nIter; it++) {
        const int p = it % NSTAGE;
        cp_wait<1>();               // stage `it` complete (it+1 may be pending)
        __syncthreads();            // all warps done with stage (it+2)%3's prior use
        if (it + 2 < nIter) load_tile((it + 2) * BK, (it + 2) % NSTAGE);

        const __half* a = sA + p * ASZ;
        const __half* b = sB + p * BSZ;
        #pragma unroll
        for (int kk = 0; kk < BK / 16; kk++) {
            wmma::fragment<wmma::matrix_a, 16, 16, 16, __half, wmma::row_major> af[4];
            wmma::fragment<wmma::matrix_b, 16, 16, 16, __half, wmma::row_major> bf[4];
            #pragma unroll
            for (int i = 0; i < 4; i++)
                wmma::load_matrix_sync(af[i], a + (wr * 64 + i * 16) * LDA + kk * 16, LDA);
            #pragma unroll
            for (int j = 0; j < 4; j++)
                wmma::load_matrix_sync(bf[j], b + (kk * 16) * LDB + wc * 64 + j * 16, LDB);
            #pragma unroll
            for (int i = 0; i < 4; i++)
                #pragma unroll
                for (int j = 0; j < 4; j++)
                    wmma::mma_sync(acc[i][j], af[i], bf[j], acc[i][j]);
        }
    }

    __syncthreads();    // all warps done reading sA/sB before Cs reuse

    #pragma unroll
    for (int i = 0; i < 4; i++)
        #pragma unroll
        for (int j = 0; j < 4; j++)
            wmma::store_matrix_sync(Cs + (wr * 64 + i * 16) * LDC + wc * 64 + j * 16,
                                    acc[i][j], LDC, wmma::mem_row_major);
    __syncthreads();

    #pragma unroll
    for (int i = 0; i < 32; i++) {   // 128x128 = 4096 float4-groups / 128 thr
        int idx = tid + i * 128;
        int r = idx >> 5, c4 = idx & 31;
        const int c = c4 * 4;
        float4 bb = *(const float4*)(bias + n0 + c);
        float vx = Cs[r * LDC + c + 0] + bb.x;
        float vy = Cs[r * LDC + c + 1] + bb.y;
        float vz = Cs[r * LDC + c + 2] + bb.z;
        float vw = Cs[r * LDC + c + 3] + bb.w;
        if (OUT_HALF) {
            __half2* dst = (__half2*)((__half*)Cout + (size_t)(m0 + r) * N + n0 + c);
            dst[0] = __floats2half2_rn(vx, vy);
            dst[1] = __floats2half2_rn(vz, vw);
        } else {
            float4 rr = *(const float4*)(res + (size_t)(m0 + r) * N + n0 + c);
            float4 o;
            o.x = vx + rr.x; o.y = vy + rr.y; o.z = vz + rr.z; o.w = vw + rr.w;
            *(float4*)((float*)Cout + (size_t)(m0 + r) * N + n0 + c) = o;
        }
    }
}

// ---------------- flash attention v4: warp-local softmax, 1 barrier/tile ----
// 256 threads (8 warps), 128-row Q tile, 64-key tiles, double-buffered cp.async
// warp w owns rows [16w, 16w+16) end-to-end: S rows, softmax rows, PV rows.
__global__ __launch_bounds__(256, 1)
void attn4_kernel(const __half* __restrict__ Qh,
                  const __half* __restrict__ Kh,
                  const __half* __restrict__ Vh,
                  const unsigned long long* __restrict__ maskp,
                  __half* __restrict__ Out) {
    constexpr int QR = 128, KT = 64, LD = 72;
    extern __shared__ char smraw[];
    unsigned long long* Mp = (unsigned long long*)smraw;        // 2*128*8 = 2048
    float* Ssf    = (float*)(smraw + 2048);                     // 128*72*4 = 36864
    float* alphaM = Ssf + QR * LD;                              // 128*16*4 = 8192
    float* mrow   = alphaM + QR * 16;                           // 512
    float* lrow   = mrow + QR;                                  // 512
    __half* Qs    = (__half*)(lrow + QR);                       // 128*72*2 = 18432
    __half* Ks    = Qs + QR * LD;                               // 2*64*72*2 = 18432
    __half* Vs    = Ks + 2 * KT * LD;                           // 18432
    __half* Ps    = Vs + 2 * KT * LD;                           // 128*72*2 = 18432

    const int tid  = threadIdx.x;
    const int warp = tid >> 5;
    const int lane = tid & 31;
    const int q0   = blockIdx.x * QR;
    const int h    = blockIdx.y;
    const int b    = blockIdx.z;

    const __half* Qg = Qh + ((size_t)b * T_ + q0) * D_ + h * DKH;

    // load Q via cp.async (128x64 halves = 1024 16B chunks)
    #pragma unroll
    for (int i = 0; i < 4; i++) {
        int idx = tid + i * 256;
        int r = idx >> 3, c8 = idx & 7;
        cp_async16(Qs + r * LD + c8 * 8, Qg + (size_t)r * D_ + c8 * 8);
    }
    cp_commit();
    if (tid < QR) { mrow[tid] = -1e30f; lrow[tid] = 0.0f; }

    wmma::fragment<wmma::accumulator, 16, 16, 16, float> o_frag[4];
    #pragma unroll
    for (int j = 0; j < 4; j++) wmma::fill_fragment(o_frag[j], 0.0f);

    auto load_kv = [&](int kt, int p) {
        const int k0 = kt * KT;
        const __half* Kg = Kh + ((size_t)b * T_ + k0) * D_ + h * DKH;
        const __half* Vg = Vh + ((size_t)b * T_ + k0) * D_ + h * DKH;
        __half* kd = Ks + p * KT * LD;
        __half* vd = Vs + p * KT * LD;
        #pragma unroll
        for (int i = 0; i < 2; i++) {       // 64x64 halves = 512 chunks each
            int idx = tid + i * 256;
            int r = idx >> 3, c8 = idx & 7;
            cp_async16(kd + r * LD + c8 * 8, Kg + (size_t)r * D_ + c8 * 8);
            cp_async16(vd + r * LD + c8 * 8, Vg + (size_t)r * D_ + c8 * 8);
        }
        if (tid < QR)
            cp_async8(&Mp[p * QR + tid],
                      &maskp[((size_t)b * T_ + q0 + tid) * (T_ / 64) + kt]);
        cp_commit();
    };

    load_kv(0, 0);
    __syncthreads();

    constexpr int NT = T_ / KT;   // 32
    for (int kt = 0; kt < NT; kt++) {
        const int p = kt & 1;
        cp_wait<0>();
        __syncthreads();          // tile kt ready; all warps' prev PV done
        if (kt + 1 < NT) load_kv(kt + 1, p ^ 1);

        const __half* kd = Ks + p * KT * LD;
        const __half* vd = Vs + p * KT * LD;

        // S = Q @ K^T : warp rows [warp*16, +16), 64 cols, k=64
        {
            wmma::fragment<wmma::matrix_a, 16, 16, 16, __half, wmma::row_major> af;
            wmma::fragment<wmma::matrix_b, 16, 16, 16, __half, wmma::col_major> bf;
            wmma::fragment<wmma::accumulator, 16, 16, 16, float> sfr[4];
            #pragma unroll
            for (int j = 0; j < 4; j++) wmma::fill_fragment(sfr[j], 0.0f);
            #pragma unroll
            for (int kk = 0; kk < 4; kk++) {
                wmma::load_matrix_sync(af, Qs + (warp * 16) * LD + kk * 16, LD);
                #pragma unroll
                for (int j = 0; j < 4; j++) {
                    wmma::load_matrix_sync(bf, kd + (j * 16) * LD + kk * 16, LD);
                    wmma::mma_sync(sfr[j], af, bf, sfr[j]);
                }
            }
            #pragma unroll
            for (int j = 0; j < 4; j++)
                wmma::store_matrix_sync(Ssf + (warp * 16) * LD + j * 16, sfr[j], LD,
                                        wmma::mem_row_major);
        }
        __syncwarp();

        // warp-local masked online softmax: 2 lanes per row, 16 rows per warp
        {
            const int r = warp * 16 + (lane >> 1);
            const int half = lane & 1;
            const int cbase = half * 32;
            const unsigned long long m64 = Mp[p * QR + r];
            float sloc[32];
            float mx = -1e30f;
            #pragma unroll
            for (int c = 0; c < 32; c++) {
                float s = Ssf[r * LD + cbase + c];
                s = ((m64 >> (cbase + c)) & 1ull) ? s : -1e30f;
                sloc[c] = s;
                mx = fmaxf(mx, s);
            }
            mx = fmaxf(mx, __shfl_xor_sync(0xffffffffu, mx, 1));
            float mold = mrow[r];
            float mnew = fmaxf(mold, mx);
            float lsum = 0.0f;
            #pragma unroll
            for (int c = 0; c < 32; c += 2) {
                float p0 = (sloc[c]     > -1e29f) ? __expf(sloc[c]     - mnew) : 0.0f;
                float p1 = (sloc[c + 1] > -1e29f) ? __expf(sloc[c + 1] - mnew) : 0.0f;
                lsum += p0 + p1;
                *(__half2*)(Ps + r * LD + cbase + c) = __floats2half2_rn(p0, p1);
            }
            lsum += __shfl_xor_sync(0xffffffffu, lsum, 1);
            float alpha = __expf(mold - mnew);
            if (half == 0) { mrow[r] = mnew; lrow[r] = lrow[r] * alpha + lsum; }
            #pragma unroll
            for (int j = 0; j < 8; j++)
                alphaM[(r << 4) + half * 8 + j] = alpha;
        }
        __syncwarp();

        // O = O*alpha + P @ V  (warp rows only)
        {
            wmma::fragment<wmma::accumulator, 16, 16, 16, float> afr;
            wmma::load_matrix_sync(afr, alphaM + warp * 16 * 16, 16, wmma::mem_row_major);
            #pragma unroll
            for (int j = 0; j < 4; j++)
                #pragma unroll
                for (int e = 0; e < afr.num_elements; e++)
                    o_frag[j].x[e] *= afr.x[e];

            wmma::fragment<wmma::matrix_a, 16, 16, 16, __half, wmma::row_major> pf;
            wmma::fragment<wmma::matrix_b, 16, 16, 16, __half, wmma::row_major> vf;
            #pragma unroll
            for (int kk = 0; kk < 4; kk++) {
                wmma::load_matrix_sync(pf, Ps + (warp * 16) * LD + kk * 16, LD);
                #pragma unroll
                for (int j = 0; j < 4; j++) {
                    wmma::load_matrix_sync(vf, vd + (kk * 16) * LD + j * 16, LD);
                    wmma::mma_sync(o_frag[j], pf, vf, o_frag[j]);
                }
            }
        }
        // next iteration's wait+syncthreads protects KV buffers
    }

    // epilogue: O / (l + 1e-15), write half
    __syncthreads();
    #pragma unroll
    for (int j = 0; j < 4; j++)
        wmma::store_matrix_sync(Ssf + (warp * 16) * LD + j * 16, o_frag[j], LD,
                                wmma::mem_row_major);
    __syncthreads();
    for (int i = tid; i < QR * DKH / 2; i += 256) {
        int r = i >> 5, c = (i & 31) * 2;
        float inv = 1.0f / (lrow[r] + 1e-15f);
        float v0 = Ssf[r * LD + c] * inv;
        float v1 = Ssf[r * LD + c + 1] * inv;
        *(__half2*)(Out + ((size_t)b * T_ + q0 + r) * D_ + h * DKH + c) =
            __floats2half2_rn(v0, v1);
    }
}

// ---------------- LayerNorm over D=1024, one block per row -----------------
__global__ void ln_kernel(const float* __restrict__ X,
                          const float* __restrict__ gamma,
                          const float* __restrict__ beta,
                          float* __restrict__ Out) {
    const int row = blockIdx.x;
    const int tid = threadIdx.x;
    const float* x = X + (size_t)row * D_;

    __shared__ float red[8];
    __shared__ float s_mu, s_inv;

    float4 v = ((const float4*)x)[tid];
    float s = v.x + v.y + v.z + v.w;
    #pragma unroll
    for (int o = 16; o > 0; o >>= 1) s += __shfl_xor_sync(0xffffffffu, s, o);
    if ((tid & 31) == 0) red[tid >> 5] = s;
    __syncthreads();
    if (tid == 0) {
        float t = 0.0f;
        #pragma unroll
        for (int i = 0; i < 8; i++) t += red[i];
        s_mu = t * (1.0f / D_);
    }
    __syncthreads();
    const float mu = s_mu;

    float dx = v.x - mu, dy = v.y - mu, dz = v.z - mu, dw = v.w - mu;
    float s2 = dx * dx + dy * dy + dz * dz + dw * dw;
    #pragma unroll
    for (int o = 16; o > 0; o >>= 1) s2 += __shfl_xor_sync(0xffffffffu, s2, o);
    if ((tid & 31) == 0) red[tid >> 5] = s2;
    __syncthreads();
    if (tid == 0) {
        float t = 0.0f;
        #pragma unroll
        for (int i = 0; i < 8; i++) t += red[i];
        s_inv = rsqrtf(t * (1.0f / D_) + 1e-5f);
    }
    __syncthreads();
    const float inv = s_inv;

    const int c = tid * 4;
    float4 g = ((const float4*)(gamma + c))[0];
    float4 bb = ((const float4*)(beta + c))[0];
    float4 o;
    o.x = dx * inv * g.x + bb.x;
    o.y = dy * inv * g.y + bb.y;
    o.z = dz * inv * g.z + bb.z;
    o.w = dw * inv * g.w + bb.w;
    ((float4*)(Out + (size_t)row * D_))[tid] = o;
}

// ---------------- launch ----------------------------------------------------
extern "C" void kernel_launch(void* const* d_in, const int* in_sizes, int n_in,
                              void* d_out, int out_size) {
    const float* q     = (const float*)d_in[0];
    const float* k     = (const float*)d_in[1];
    const float* v     = (const float*)d_in[2];
    const int*   mask  = (const int*)  d_in[3];
    const float* Wq    = (const float*)d_in[4];
    const float* bq    = (const float*)d_in[5];
    const float* Wk    = (const float*)d_in[6];
    const float* bk    = (const float*)d_in[7];
    const float* Wv    = (const float*)d_in[8];
    const float* bv    = (const float*)d_in[9];
    const float* Wo    = (const float*)d_in[10];
    const float* bo    = (const float*)d_in[11];
    const float* gamma = (const float*)d_in[12];
    const float* beta  = (const float*)d_in[13];
    float* out = (float*)d_out;

    __half *qx, *kx, *vx, *wh, *qh, *kh, *vh, *ao;
    float *xb;
    unsigned long long* mp;
    cudaGetSymbolAddress((void**)&qx, g_qx);
    cudaGetSymbolAddress((void**)&kx, g_kx);
    cudaGetSymbolAddress((void**)&vx, g_vx);
    cudaGetSymbolAddress((void**)&wh, g_wh);
    cudaGetSymbolAddress((void**)&qh, g_qh);
    cudaGetSymbolAddress((void**)&kh, g_kh);
    cudaGetSymbolAddress((void**)&vh, g_vh);
    cudaGetSymbolAddress((void**)&ao, g_ao);
    cudaGetSymbolAddress((void**)&xb, g_x);
    cudaGetSymbolAddress((void**)&mp, g_maskp);

    __half* wq_h = wh;
    __half* wk_h = wh + (size_t)D_ * D_;
    __half* wv_h = wh + 2 * (size_t)D_ * D_;
    __half* wo_h = wh + 3 * (size_t)D_ * D_;

    const int M = B_ * T_;   // 8192
    const int N = D_;        // 1024
    const int K = D_;        // 1024

    // pack mask to bits
    {
        const int words = B_ * T_ * (T_ / 64);
        pack_mask_kernel<<<words * 32 / 256, 256>>>(mask, mp);
    }

    // fp32 -> fp16 conversions (RTN), batched
    {
        const int n4a = (B_ * T_ * D_) / 4;   // 2,097,152
        dim3 ga(n4a / 256, 3);
        f2h3_kernel<<<ga, 256>>>(q, qx, k, kx, v, vx, n4a);
        const int n4w = (D_ * D_) / 4;        // 262,144
        dim3 gw(n4w / 256, 4);
        f2h4_kernel<<<gw, 256>>>(Wq, Wk, Wv, Wo, wh, n4w);
    }

    // fp16 WMMA GEMMs (v5: 64x64 warp tiles, 3-stage)
    const int gemm_smem = 3 * (128 * 72 + 64 * 136) * 2;   // 107520 B
    cudaFuncSetAttribute(gemm5_kernel<true>,
                         cudaFuncAttributeMaxDynamicSharedMemorySize, gemm_smem);
    cudaFuncSetAttribute(gemm5_kernel<false>,
                         cudaFuncAttributeMaxDynamicSharedMemorySize, gemm_smem);

    dim3 gg(N / 128, M / 128);      // (8, 64)
    gemm5_kernel<true><<<gg, 128, gemm_smem>>>(qx, wq_h, bq, nullptr, qh, M, N, K);
    gemm5_kernel<true><<<gg, 128, gemm_smem>>>(kx, wk_h, bk, nullptr, kh, M, N, K);
    gemm5_kernel<true><<<gg, 128, gemm_smem>>>(vx, wv_h, bv, nullptr, vh, M, N, K);

    const int attn_smem = 2048 + 36864 + 8192 + 512 + 512
                        + 18432 + 18432 + 18432 + 18432;   // 121856 B
    cudaFuncSetAttribute(attn4_kernel,
                         cudaFuncAttributeMaxDynamicSharedMemorySize, attn_smem);
    dim3 ga(T_ / 128, H_, B_);      // (16, 16, 4)
    attn4_kernel<<<ga, 256, attn_smem>>>(qh, kh, vh, mp, ao);

    gemm5_kernel<false><<<gg, 128, gemm_smem>>>(ao, wo_h, bo, q, xb, M, N, K);

    ln_kernel<<<M, 256>>>(xb, gamma, beta, out);
}

// round 7
// speedup vs baseline: 5.9396x; 1.2988x over previous
#include <cuda_runtime.h>
#include <cuda_fp16.h>
#include <mma.h>
#include <cstdint>

using namespace nvcuda;

#define B_  4
#define T_  2048
#define D_  1024
#define H_  16
#define DKH 64

// ---------------- scratch (static device globals; no runtime alloc) --------
__device__ __half g_qx[(size_t)B_ * T_ * D_];   // fp16 inputs
__device__ __half g_kx[(size_t)B_ * T_ * D_];
__device__ __half g_vx[(size_t)B_ * T_ * D_];
__device__ __half g_wh[4][(size_t)D_ * D_];     // fp16 weights [K,N]
__device__ __half g_qh[(size_t)B_ * T_ * D_];   // fp16 projections
__device__ __half g_kh[(size_t)B_ * T_ * D_];
__device__ __half g_vh[(size_t)B_ * T_ * D_];
__device__ __half g_ao[(size_t)B_ * T_ * D_];   // fp16 attention output
__device__ float  g_x [(size_t)B_ * T_ * D_];   // fp32 pre-LN
__device__ unsigned long long g_maskp[(size_t)B_ * T_ * (T_ / 64)];  // 2MB

// ---------------- cp.async / ldmatrix / mma helpers -------------------------
__device__ __forceinline__ void cp_async16(void* smem, const void* gmem) {
    unsigned s = (unsigned)__cvta_generic_to_shared(smem);
    asm volatile("cp.async.cg.shared.global [%0], [%1], 16;\n" :: "r"(s), "l"(gmem));
}
__device__ __forceinline__ void cp_async8(void* smem, const void* gmem) {
    unsigned s = (unsigned)__cvta_generic_to_shared(smem);
    asm volatile("cp.async.ca.shared.global [%0], [%1], 8;\n" :: "r"(s), "l"(gmem));
}
__device__ __forceinline__ void cp_commit() {
    asm volatile("cp.async.commit_group;\n");
}
template<int N>
__device__ __forceinline__ void cp_wait() {
    asm volatile("cp.async.wait_group %0;\n" :: "n"(N));
}
__device__ __forceinline__ void ldsm4(uint32_t* r, uint32_t a) {
    asm volatile("ldmatrix.sync.aligned.m8n8.x4.shared.b16 {%0,%1,%2,%3}, [%4];"
                 : "=r"(r[0]), "=r"(r[1]), "=r"(r[2]), "=r"(r[3]) : "r"(a));
}
__device__ __forceinline__ void ldsm4t(uint32_t* r, uint32_t a) {
    asm volatile("ldmatrix.sync.aligned.m8n8.x4.trans.shared.b16 {%0,%1,%2,%3}, [%4];"
                 : "=r"(r[0]), "=r"(r[1]), "=r"(r[2]), "=r"(r[3]) : "r"(a));
}
__device__ __forceinline__ void mma16816(float* c, const uint32_t* a, const uint32_t* b) {
    asm volatile(
        "mma.sync.aligned.m16n8k16.row.col.f32.f16.f16.f32 "
        "{%0,%1,%2,%3}, {%4,%5,%6,%7}, {%8,%9}, {%0,%1,%2,%3};"
        : "+f"(c[0]), "+f"(c[1]), "+f"(c[2]), "+f"(c[3])
        : "r"(a[0]), "r"(a[1]), "r"(a[2]), "r"(a[3]), "r"(b[0]), "r"(b[1]));
}
__device__ __forceinline__ uint32_t h2u(float a, float b) {
    __half2 h = __floats2half2_rn(a, b);
    return *reinterpret_cast<uint32_t*>(&h);
}

// ---------------- mask bit-pack: one warp per 64-bit word -------------------
__global__ void pack_mask_kernel(const int* __restrict__ mask,
                                 unsigned long long* __restrict__ mp) {
    const int gw   = (blockIdx.x * blockDim.x + threadIdx.x) >> 5;
    const int lane = threadIdx.x & 31;
    const int* src = mask + (size_t)gw * 64;
    int v0 = src[lane];
    int v1 = src[lane + 32];
    unsigned lo = __ballot_sync(0xffffffffu, v0 != 0);
    unsigned hi = __ballot_sync(0xffffffffu, v1 != 0);
    if (lane == 0) mp[gw] = ((unsigned long long)hi << 32) | lo;
}

// ---------------- fp32 -> fp16 convert (batched) ----------------------------
__global__ void f2h3_kernel(const float* __restrict__ s0, __half* __restrict__ d0,
                            const float* __restrict__ s1, __half* __restrict__ d1,
                            const float* __restrict__ s2, __half* __restrict__ d2,
                            int n4) {
    int i = blockIdx.x * blockDim.x + threadIdx.x;
    if (i >= n4) return;
    const float* in = (blockIdx.y == 0) ? s0 : (blockIdx.y == 1) ? s1 : s2;
    __half* out     = (blockIdx.y == 0) ? d0 : (blockIdx.y == 1) ? d1 : d2;
    float4 v = ((const float4*)in)[i];
    ((__half2*)out)[2 * i + 0] = __floats2half2_rn(v.x, v.y);
    ((__half2*)out)[2 * i + 1] = __floats2half2_rn(v.z, v.w);
}
__global__ void f2h4_kernel(const float* __restrict__ s0, const float* __restrict__ s1,
                            const float* __restrict__ s2, const float* __restrict__ s3,
                            __half* __restrict__ dst, int n4) {
    int i = blockIdx.x * blockDim.x + threadIdx.x;
    if (i >= n4) return;
    const float* in = (blockIdx.y == 0) ? s0 : (blockIdx.y == 1) ? s1
                    : (blockIdx.y == 2) ? s2 : s3;
    __half* out = dst + (size_t)blockIdx.y * D_ * D_;
    float4 v = ((const float4*)in)[i];
    ((__half2*)out)[2 * i + 0] = __floats2half2_rn(v.x, v.y);
    ((__half2*)out)[2 * i + 1] = __floats2half2_rn(v.z, v.w);
}

// ---------------- fp16 WMMA GEMM v5 (unchanged from round 6) ----------------
template<bool OUT_HALF>
__global__ __launch_bounds__(128, 2)
void gemm5_kernel(const __half* __restrict__ A,
                  const __half* __restrict__ W,
                  const float* __restrict__ bias,
                  const float* __restrict__ res,
                  void* __restrict__ Cout,
                  int M, int N, int K) {
    constexpr int BM = 128, BN = 128, BK = 64;
    constexpr int LDA = 72, LDB = 136, LDC = 132;
    constexpr int ASZ = BM * LDA;
    constexpr int BSZ = BK * LDB;
    constexpr int NSTAGE = 3;

    extern __shared__ char smraw[];
    __half* sA = (__half*)smraw;
    __half* sB = sA + NSTAGE * ASZ;
    float*  Cs = (float*)smraw;

    const int tid  = threadIdx.x;
    const int warp = tid >> 5;
    const int wr   = warp & 1;
    const int wc   = warp >> 1;
    const int m0   = blockIdx.y * BM;
    const int n0   = blockIdx.x * BN;

    wmma::fragment<wmma::accumulator, 16, 16, 16, float> acc[4][4];
    #pragma unroll
    for (int i = 0; i < 4; i++)
        #pragma unroll
        for (int j = 0; j < 4; j++)
            wmma::fill_fragment(acc[i][j], 0.0f);

    auto load_tile = [&](int k0, int p) {
        __half* a = sA + p * ASZ;
        __half* b = sB + p * BSZ;
        #pragma unroll
        for (int i = 0; i < 8; i++) {
            int idx = tid + i * 128;
            int r = idx >> 3, c8 = idx & 7;
            cp_async16(a + r * LDA + c8 * 8, A + (size_t)(m0 + r) * K + k0 + c8 * 8);
        }
        #pragma unroll
        for (int i = 0; i < 8; i++) {
            int idx = tid + i * 128;
            int r = idx >> 4, c8 = idx & 15;
            cp_async16(b + r * LDB + c8 * 8, W + (size_t)(k0 + r) * N + n0 + c8 * 8);
        }
        cp_commit();
    };

    const int nIter = K / BK;
    load_tile(0, 0);
    load_tile(BK, 1);

    for (int it = 0; it < nIter; it++) {
        const int p = it % NSTAGE;
        cp_wait<1>();
        __syncthreads();
        if (it + 2 < nIter) load_tile((it + 2) * BK, (it + 2) % NSTAGE);

        const __half* a = sA + p * ASZ;
        const __half* b = sB + p * BSZ;
        #pragma unroll
        for (int kk = 0; kk < BK / 16; kk++) {
            wmma::fragment<wmma::matrix_a, 16, 16, 16, __half, wmma::row_major> af[4];
            wmma::fragment<wmma::matrix_b, 16, 16, 16, __half, wmma::row_major> bf[4];
            #pragma unroll
            for (int i = 0; i < 4; i++)
                wmma::load_matrix_sync(af[i], a + (wr * 64 + i * 16) * LDA + kk * 16, LDA);
            #pragma unroll
            for (int j = 0; j < 4; j++)
                wmma::load_matrix_sync(bf[j], b + (kk * 16) * LDB + wc * 64 + j * 16, LDB);
            #pragma unroll
            for (int i = 0; i < 4; i++)
                #pragma unroll
                for (int j = 0; j < 4; j++)
                    wmma::mma_sync(acc[i][j], af[i], bf[j], acc[i][j]);
        }
    }

    __syncthreads();

    #pragma unroll
    for (int i = 0; i < 4; i++)
        #pragma unroll
        for (int j = 0; j < 4; j++)
            wmma::store_matrix_sync(Cs + (wr * 64 + i * 16) * LDC + wc * 64 + j * 16,
                                    acc[i][j], LDC, wmma::mem_row_major);
    __syncthreads();

    #pragma unroll
    for (int i = 0; i < 32; i++) {
        int idx = tid + i * 128;
        int r = idx >> 5, c4 = idx & 31;
        const int c = c4 * 4;
        float4 bb = *(const float4*)(bias + n0 + c);
        float vx = Cs[r * LDC + c + 0] + bb.x;
        float vy = Cs[r * LDC + c + 1] + bb.y;
        float vz = Cs[r * LDC + c + 2] + bb.z;
        float vw = Cs[r * LDC + c + 3] + bb.w;
        if (OUT_HALF) {
            __half2* dst = (__half2*)((__half*)Cout + (size_t)(m0 + r) * N + n0 + c);
            dst[0] = __floats2half2_rn(vx, vy);
            dst[1] = __floats2half2_rn(vz, vw);
        } else {
            float4 rr = *(const float4*)(res + (size_t)(m0 + r) * N + n0 + c);
            float4 o;
            o.x = vx + rr.x; o.y = vy + rr.y; o.z = vz + rr.z; o.w = vw + rr.w;
            *(float4*)((float*)Cout + (size_t)(m0 + r) * N + n0 + c) = o;
        }
    }
}

// ---------------- flash attention v5: register softmax (mma.sync) -----------
// 256 threads, 8 warps; warp owns 16 Q rows. KT=64 keys/tile, double-buffered.
// S and O live entirely in mma fragments; softmax via quad shfl. 1 barrier/tile.
__global__ __launch_bounds__(256, 2)
void attn5_kernel(const __half* __restrict__ Qh,
                  const __half* __restrict__ Kh,
                  const __half* __restrict__ Vh,
                  const unsigned long long* __restrict__ maskp,
                  __half* __restrict__ Out) {
    constexpr int QR = 128, KT = 64, LD = 72;
    constexpr int NT = T_ / KT;   // 32

    extern __shared__ char smraw[];
    unsigned long long* Mp = (unsigned long long*)smraw;        // 2*128*8 = 2048
    __half* Qs = (__half*)(smraw + 2048);                       // 128*72*2 = 18432
    __half* Ks = Qs + QR * LD;                                  // 2*64*72*2 = 18432
    __half* Vs = Ks + 2 * KT * LD;                              // 18432
    // total 57344 B

    const int tid  = threadIdx.x;
    const int warp = tid >> 5;
    const int lane = tid & 31;
    const int q0   = blockIdx.x * QR;
    const int h    = blockIdx.y;
    const int b    = blockIdx.z;

    const int lr  = lane & 15;          // ldmatrix row-in-16
    const int l7  = lane & 7;
    const int lh  = (lane >> 4) & 1;    // matrix-pair select
    const int l8  = (lane >> 3) & 1;
    const int gr  = lane >> 2;          // quad row
    const int t4  = lane & 3;           // thread-in-quad

    const __half* Qg = Qh + ((size_t)b * T_ + q0) * D_ + h * DKH;

    // Q -> smem (128x64 halves = 1024 16B chunks)
    #pragma unroll
    for (int i = 0; i < 4; i++) {
        int idx = tid + i * 256;
        int r = idx >> 3, c8 = idx & 7;
        cp_async16(Qs + r * LD + c8 * 8, Qg + (size_t)r * D_ + c8 * 8);
    }

    auto load_kv = [&](int kt, int p) {
        const int k0 = kt * KT;
        const __half* Kg = Kh + ((size_t)b * T_ + k0) * D_ + h * DKH;
        const __half* Vg = Vh + ((size_t)b * T_ + k0) * D_ + h * DKH;
        __half* kd = Ks + p * KT * LD;
        __half* vd = Vs + p * KT * LD;
        #pragma unroll
        for (int i = 0; i < 2; i++) {       // 64x64 halves = 512 chunks each
            int idx = tid + i * 256;
            int r = idx >> 3, c8 = idx & 7;
            cp_async16(kd + r * LD + c8 * 8, Kg + (size_t)r * D_ + c8 * 8);
            cp_async16(vd + r * LD + c8 * 8, Vg + (size_t)r * D_ + c8 * 8);
        }
        if (tid < QR)
            cp_async8(&Mp[p * QR + tid],
                      &maskp[((size_t)b * T_ + q0 + tid) * (T_ / 64) + kt]);
        cp_commit();
    };

    load_kv(0, 0);      // commits Q chunks too

    const uint32_t QsB = (uint32_t)__cvta_generic_to_shared(Qs);
    const uint32_t KsB = (uint32_t)__cvta_generic_to_shared(Ks);
    const uint32_t VsB = (uint32_t)__cvta_generic_to_shared(Vs);

    uint32_t qa[4][4];                  // Q A-fragments (dk chunks)
    float oc[8][4];                     // O accum: 8 n-blocks of 8 dk cols
    #pragma unroll
    for (int j = 0; j < 8; j++)
        #pragma unroll
        for (int e = 0; e < 4; e++) oc[j][e] = 0.0f;

    float m0r = -1e30f, m1r = -1e30f;   // row max (rows gr, gr+8)
    float l0r = 0.0f,  l1r = 0.0f;      // row sum

    for (int kt = 0; kt < NT; kt++) {
        const int p = kt & 1;
        cp_wait<0>();
        __syncthreads();
        if (kt == 0) {
            #pragma unroll
            for (int kk = 0; kk < 4; kk++)
                ldsm4(qa[kk], QsB + 2u * ((warp * 16 + lr) * LD + kk * 16 + lh * 8));
        }
        if (kt + 1 < NT) load_kv(kt + 1, p ^ 1);

        const uint32_t KdB = KsB + (uint32_t)(p * KT * LD * 2);
        const uint32_t VdB = VsB + (uint32_t)(p * KT * LD * 2);

        // ---- S = Q @ K^T (16 rows x 64 keys), fragments sc[8] ----
        float sc[8][4];
        #pragma unroll
        for (int j = 0; j < 8; j++)
            #pragma unroll
            for (int e = 0; e < 4; e++) sc[j][e] = 0.0f;

        #pragma unroll
        for (int kk = 0; kk < 4; kk++) {
            #pragma unroll
            for (int jp = 0; jp < 4; jp++) {
                uint32_t kb[4];
                ldsm4(kb, KdB + 2u * ((16 * jp + l7 + lh * 8) * LD + kk * 16 + l8 * 8));
                mma16816(sc[2 * jp],     qa[kk], kb);
                mma16816(sc[2 * jp + 1], qa[kk], kb + 2);
            }
        }

        // ---- register softmax (rows gr=r0, gr+8=r1 of this warp tile) ----
        const unsigned long long mm0 = Mp[p * QR + warp * 16 + gr];
        const unsigned long long mm1 = Mp[p * QR + warp * 16 + gr + 8];
        float mx0 = -1e30f, mx1 = -1e30f;
        #pragma unroll
        for (int j = 0; j < 8; j++) {
            const int c0 = 8 * j + 2 * t4;
            sc[j][0] = ((mm0 >> c0) & 1ull)       ? sc[j][0] : -1e30f;
            sc[j][1] = ((mm0 >> (c0 + 1)) & 1ull) ? sc[j][1] : -1e30f;
            sc[j][2] = ((mm1 >> c0) & 1ull)       ? sc[j][2] : -1e30f;
            sc[j][3] = ((mm1 >> (c0 + 1)) & 1ull) ? sc[j][3] : -1e30f;
            mx0 = fmaxf(mx0, fmaxf(sc[j][0], sc[j][1]));
            mx1 = fmaxf(mx1, fmaxf(sc[j][2], sc[j][3]));
        }
        mx0 = fmaxf(mx0, __shfl_xor_sync(0xffffffffu, mx0, 1));
        mx0 = fmaxf(mx0, __shfl_xor_sync(0xffffffffu, mx0, 2));
        mx1 = fmaxf(mx1, __shfl_xor_sync(0xffffffffu, mx1, 1));
        mx1 = fmaxf(mx1, __shfl_xor_sync(0xffffffffu, mx1, 2));

        const float mn0 = fmaxf(m0r, mx0);
        const float mn1 = fmaxf(m1r, mx1);
        const float al0 = __expf(m0r - mn0);
        const float al1 = __expf(m1r - mn1);
        m0r = mn0; m1r = mn1;

        uint32_t pa[4][4];
        float rs0 = 0.0f, rs1 = 0.0f;
        #pragma unroll
        for (int j = 0; j < 8; j++) {
            float p0 = (sc[j][0] > -1e29f) ? __expf(sc[j][0] - mn0) : 0.0f;
            float p1 = (sc[j][1] > -1e29f) ? __expf(sc[j][1] - mn0) : 0.0f;
            float p2 = (sc[j][2] > -1e29f) ? __expf(sc[j][2] - mn1) : 0.0f;
            float p3 = (sc[j][3] > -1e29f) ? __expf(sc[j][3] - mn1) : 0.0f;
            rs0 += p0 + p1;
            rs1 += p2 + p3;
            const int kk = j >> 1, lohalf = (j & 1) << 1;
            pa[kk][lohalf + 0] = h2u(p0, p1);
            pa[kk][lohalf + 1] = h2u(p2, p3);
        }
        // NOTE: pa layout: pa[kk] = {P[r0][16kk+2t..], P[r1][..], P[r0][16kk+8+2t..], P[r1][..]}
        // matches m16n8k16 A-fragment {a0(r0,klo), a1(r1,klo), a2(r0,khi), a3(r1,khi)}
        rs0 += __shfl_xor_sync(0xffffffffu, rs0, 1);
        rs0 += __shfl_xor_sync(0xffffffffu, rs0, 2);
        rs1 += __shfl_xor_sync(0xffffffffu, rs1, 1);
        rs1 += __shfl_xor_sync(0xffffffffu, rs1, 2);
        l0r = l0r * al0 + rs0;
        l1r = l1r * al1 + rs1;

        #pragma unroll
        for (int j = 0; j < 8; j++) {
            oc[j][0] *= al0; oc[j][1] *= al0;
            oc[j][2] *= al1; oc[j][3] *= al1;
        }

        // ---- O += P @ V ----
        #pragma unroll
        for (int kk = 0; kk < 4; kk++) {
            #pragma unroll
            for (int jp = 0; jp < 4; jp++) {
                uint32_t vb[4];
                ldsm4t(vb, VdB + 2u * ((16 * kk + lr) * LD + 16 * jp + lh * 8));
                mma16816(oc[2 * jp],     pa[kk], vb);
                mma16816(oc[2 * jp + 1], pa[kk], vb + 2);
            }
        }
    }

    // ---- epilogue: O / (l + 1e-15), direct to gmem (fp16) ----
    const float inv0 = 1.0f / (l0r + 1e-15f);
    const float inv1 = 1.0f / (l1r + 1e-15f);
    const size_t row0 = (size_t)b * T_ + q0 + warp * 16 + gr;
    __half* o0 = Out + row0 * D_ + h * DKH;
    __half* o1 = o0 + 8 * D_;
    #pragma unroll
    for (int j = 0; j < 8; j++) {
        const int c = 8 * j + 2 * t4;
        *(__half2*)(o0 + c) = __floats2half2_rn(oc[j][0] * inv0, oc[j][1] * inv0);
        *(__half2*)(o1 + c) = __floats2half2_rn(oc[j][2] * inv1, oc[j][3] * inv1);
    }
}

// ---------------- LayerNorm over D=1024, one block per row -----------------
__global__ void ln_kernel(const float* __restrict__ X,
                          const float* __restrict__ gamma,
                          const float* __restrict__ beta,
                          float* __restrict__ Out) {
    const int row = blockIdx.x;
    const int tid = threadIdx.x;
    const float* x = X + (size_t)row * D_;

    __shared__ float red[8];
    __shared__ float s_mu, s_inv;

    float4 v = ((const float4*)x)[tid];
    float s = v.x + v.y + v.z + v.w;
    #pragma unroll
    for (int o = 16; o > 0; o >>= 1) s += __shfl_xor_sync(0xffffffffu, s, o);
    if ((tid & 31) == 0) red[tid >> 5] = s;
    __syncthreads();
    if (tid == 0) {
        float t = 0.0f;
        #pragma unroll
        for (int i = 0; i < 8; i++) t += red[i];
        s_mu = t * (1.0f / D_);
    }
    __syncthreads();
    const float mu = s_mu;

    float dx = v.x - mu, dy = v.y - mu, dz = v.z - mu, dw = v.w - mu;
    float s2 = dx * dx + dy * dy + dz * dz + dw * dw;
    #pragma unroll
    for (int o = 16; o > 0; o >>= 1) s2 += __shfl_xor_sync(0xffffffffu, s2, o);
    if ((tid & 31) == 0) red[tid >> 5] = s2;
    __syncthreads();
    if (tid == 0) {
        float t = 0.0f;
        #pragma unroll
        for (int i = 0; i < 8; i++) t += red[i];
        s_inv = rsqrtf(t * (1.0f / D_) + 1e-5f);
    }
    __syncthreads();
    const float inv = s_inv;

    const int c = tid * 4;
    float4 g = ((const float4*)(gamma + c))[0];
    float4 bb = ((const float4*)(beta + c))[0];
    float4 o;
    o.x = dx * inv * g.x + bb.x;
    o.y = dy * inv * g.y + bb.y;
    o.z = dz * inv * g.z + bb.z;
    o.w = dw * inv * g.w + bb.w;
    ((float4*)(Out + (size_t)row * D_))[tid] = o;
}

// ---------------- launch ----------------------------------------------------
extern "C" void kernel_launch(void* const* d_in, const int* in_sizes, int n_in,
                              void* d_out, int out_size) {
    const float* q     = (const float*)d_in[0];
    const float* k     = (const float*)d_in[1];
    const float* v     = (const float*)d_in[2];
    const int*   mask  = (const int*)  d_in[3];
    const float* Wq    = (const float*)d_in[4];
    const float* bq    = (const float*)d_in[5];
    const float* Wk    = (const float*)d_in[6];
    const float* bk    = (const float*)d_in[7];
    const float* Wv    = (const float*)d_in[8];
    const float* bv    = (const float*)d_in[9];
    const float* Wo    = (const float*)d_in[10];
    const float* bo    = (const float*)d_in[11];
    const float* gamma = (const float*)d_in[12];
    const float* beta  = (const float*)d_in[13];
    float* out = (float*)d_out;

    __half *qx, *kx, *vx, *wh, *qh, *kh, *vh, *ao;
    float *xb;
    unsigned long long* mp;
    cudaGetSymbolAddress((void**)&qx, g_qx);
    cudaGetSymbolAddress((void**)&kx, g_kx);
    cudaGetSymbolAddress((void**)&vx, g_vx);
    cudaGetSymbolAddress((void**)&wh, g_wh);
    cudaGetSymbolAddress((void**)&qh, g_qh);
    cudaGetSymbolAddress((void**)&kh, g_kh);
    cudaGetSymbolAddress((void**)&vh, g_vh);
    cudaGetSymbolAddress((void**)&ao, g_ao);
    cudaGetSymbolAddress((void**)&xb, g_x);
    cudaGetSymbolAddress((void**)&mp, g_maskp);

    __half* wq_h = wh;
    __half* wk_h = wh + (size_t)D_ * D_;
    __half* wv_h = wh + 2 * (size_t)D_ * D_;
    __half* wo_h = wh + 3 * (size_t)D_ * D_;

    const int M = B_ * T_;   // 8192
    const int N = D_;        // 1024
    const int K = D_;        // 1024

    // pack mask to bits
    {
        const int words = B_ * T_ * (T_ / 64);
        pack_mask_kernel<<<words * 32 / 256, 256>>>(mask, mp);
    }

    // fp32 -> fp16 conversions (RTN), batched
    {
        const int n4a = (B_ * T_ * D_) / 4;
        dim3 ga(n4a / 256, 3);
        f2h3_kernel<<<ga, 256>>>(q, qx, k, kx, v, vx, n4a);
        const int n4w = (D_ * D_) / 4;
        dim3 gw(n4w / 256, 4);
        f2h4_kernel<<<gw, 256>>>(Wq, Wk, Wv, Wo, wh, n4w);
    }

    // fp16 WMMA GEMMs
    const int gemm_smem = 3 * (128 * 72 + 64 * 136) * 2;   // 107520 B
    cudaFuncSetAttribute(gemm5_kernel<true>,
                         cudaFuncAttributeMaxDynamicSharedMemorySize, gemm_smem);
    cudaFuncSetAttribute(gemm5_kernel<false>,
                         cudaFuncAttributeMaxDynamicSharedMemorySize, gemm_smem);

    dim3 gg(N / 128, M / 128);      // (8, 64)
    gemm5_kernel<true><<<gg, 128, gemm_smem>>>(qx, wq_h, bq, nullptr, qh, M, N, K);
    gemm5_kernel<true><<<gg, 128, gemm_smem>>>(kx, wk_h, bk, nullptr, kh, M, N, K);
    gemm5_kernel<true><<<gg, 128, gemm_smem>>>(vx, wv_h, bv, nullptr, vh, M, N, K);

    // flash attention v5 (register softmax)
    const int attn_smem = 2048 + 3 * (128 * 72 * 2);   // 57344 B
    cudaFuncSetAttribute(attn5_kernel,
                         cudaFuncAttributeMaxDynamicSharedMemorySize, attn_smem);
    dim3 ga(T_ / 128, H_, B_);      // (16, 16, 4)
    attn5_kernel<<<ga, 256, attn_smem>>>(qh, kh, vh, mp, ao);

    gemm5_kernel<false><<<gg, 128, gemm_smem>>>(ao, wo_h, bo, q, xb, M, N, K);

    ln_kernel<<<M, 256>>>(xb, gamma, beta, out);
}